// round 4
// baseline (speedup 1.0000x reference)
#include <cuda_runtime.h>

#define BS 32
#define PP 128
#define RR 16
#define DD 1024
#define RHO 0.97f

// ---------------- scratch (no allocations allowed) ----------------
__device__ float g_C[BS * PP * DD];      // k_cand pre-normalization (16 MB)
__device__ float g_w[BS * PP];           // w[b,p] = gate * suffix-prod(a_keep)
__device__ float g_coefK[BS * PP];       // w / row_norm
__device__ float g_Atot[BS];             // prod of all a_keep
__device__ float g_wsum[BS];             // sum_p w[b,p]
__device__ float g_hbar[BS * DD];        // sum_p w[b,p] * h[b,p,:]
__device__ float g_eligK[BS * DD];       // sum_p coefK * C  (shared across R)
__device__ float g_eligV[BS * DD];       // hbar @ Wv + wsum*bv (shared across R)

// ---------------- 1) per-batch coefficients ----------------
__global__ void coeff_kernel(const float* __restrict__ surprise,
                             const unsigned int* __restrict__ mask) {
    int b = blockIdx.x, p = threadIdx.x;  // 128 threads
    __shared__ float a_s[PP], c_s[PP], w_s[PP];
    float g = fminf(fmaxf(surprise[b * PP + p] * 0.2f, 0.0f), 1.0f);
    float a = (mask[b * PP + p] != 0u) ? 0.0f : RHO;
    a_s[p] = a;
    __syncthreads();
    if (p == 0) {
        float c = 1.0f;
        for (int q = PP - 1; q >= 0; --q) { c_s[q] = c; c *= a_s[q]; }
        g_Atot[b] = c;
    }
    __syncthreads();
    float w = g * c_s[p];
    w_s[p] = w;
    g_w[b * PP + p] = w;
    __syncthreads();
    if (p == 0) {
        float s = 0.0f;
        for (int q = 0; q < PP; q++) s += w_s[q];
        g_wsum[b] = s;
    }
}

// ---------------- 2) hbar[b,d] = sum_p w[b,p] * h[b,p,d] ----------------
__global__ __launch_bounds__(256) void hbar_kernel(const float* __restrict__ h) {
    int b = blockIdx.x;
    int d = blockIdx.y * 256 + threadIdx.x;
    __shared__ float cs[PP];
    if (threadIdx.x < PP) cs[threadIdx.x] = g_w[b * PP + threadIdx.x];
    __syncthreads();
    const float* sp = h + (size_t)b * PP * DD + d;
    float acc = 0.0f;
#pragma unroll 8
    for (int p = 0; p < PP; p++) acc += cs[p] * sp[(size_t)p * DD];
    g_hbar[b * DD + d] = acc;
}

// ---------------- 3) big SGEMM: g_C = X @ Wk + bk  (4096x1024x1024) ----------------
// BM=128, BN=64, BK=16, 256 threads, per-thread 8x4 micro-tile.
// Register-prefetch software pipeline: next K-slab's global loads are issued
// before the current slab's FFMA burst, hiding global latency behind compute.
__global__ __launch_bounds__(256) void sgemm_kernel(const float* __restrict__ A,
                                                    const float* __restrict__ B,
                                                    const float* __restrict__ bias) {
    __shared__ float As[16][128];
    __shared__ float Bs[16][64];
    int tid = threadIdx.x;
    int tx = tid & 15;        // 0..15  (N dir, 4 cols each)
    int ty = tid >> 4;        // 0..15  (M dir, 8 rows each)
    int row0 = blockIdx.y * 128;
    int col0 = blockIdx.x * 64;

    float acc[8][4];
#pragma unroll
    for (int i = 0; i < 8; i++)
#pragma unroll
        for (int j = 0; j < 4; j++) acc[i][j] = 0.0f;

    const float4* Af = (const float4*)A;  // 256 float4 per row
    const float4* Bf = (const float4*)B;

    // A-load geometry (fixed per thread): 2 float4 loads per slab
    int ar0 = tid >> 2;               // 0..63
    int ar1 = ar0 + 64;               // 64..127
    int akq = tid & 3;                // float4 within k-slab
    // B-load geometry: 1 float4 per thread
    int br = tid >> 4;                // 0..15
    int bc4 = tid & 15;               // 0..15

    const float4* Ap0 = Af + (size_t)(row0 + ar0) * 256 + akq;
    const float4* Ap1 = Af + (size_t)(row0 + ar1) * 256 + akq;
    const float4* Bp = Bf + (size_t)br * 256 + (col0 >> 2) + bc4;

    // prologue: load slab 0
    float4 a0v = Ap0[0];
    float4 a1v = Ap1[0];
    float4 bv0 = Bp[0];

    for (int k0 = 0; k0 < 1024; k0 += 16) {
        // store current slab to smem
        As[akq * 4 + 0][ar0] = a0v.x; As[akq * 4 + 1][ar0] = a0v.y;
        As[akq * 4 + 2][ar0] = a0v.z; As[akq * 4 + 3][ar0] = a0v.w;
        As[akq * 4 + 0][ar1] = a1v.x; As[akq * 4 + 1][ar1] = a1v.y;
        As[akq * 4 + 2][ar1] = a1v.z; As[akq * 4 + 3][ar1] = a1v.w;
        *(float4*)&Bs[br][bc4 * 4] = bv0;
        __syncthreads();

        // prefetch next slab into registers (overlaps FFMA burst below)
        if (k0 + 16 < 1024) {
            a0v = Ap0[(k0 >> 2) + 4];
            a1v = Ap1[(k0 >> 2) + 4];
            bv0 = Bp[((size_t)(k0 + 16)) * 64 + 0];   // (k0+16) rows * 256 f4 offset... see note
        }
        // NOTE: Bp advances by 16 rows * 256 float4 = 4096 float4 per slab
        // (computed via explicit pointer below to avoid the expression above)
        __syncthreads();
        // the __syncthreads above is wrong placement; real sync happens after FFMA
        // -- replaced by correct structure below
        break;
    }

    // ---- correct, fully unrolled pipeline (the loop above exits after setup) ----
    for (int k0 = 0;;) {
        // smem now holds slab k0 (stored in first iteration above for k0=0)
        // FFMA burst on slab k0
#pragma unroll
        for (int k = 0; k < 16; k++) {
            float4 va0 = *(const float4*)&As[k][ty * 8];
            float4 va1 = *(const float4*)&As[k][ty * 8 + 4];
            float4 vb = *(const float4*)&Bs[k][tx * 4];
            float am[8] = {va0.x, va0.y, va0.z, va0.w, va1.x, va1.y, va1.z, va1.w};
            float bn[4] = {vb.x, vb.y, vb.z, vb.w};
#pragma unroll
            for (int i = 0; i < 8; i++)
#pragma unroll
                for (int j = 0; j < 4; j++) acc[i][j] += am[i] * bn[j];
        }
        k0 += 16;
        if (k0 >= 1024) break;
        __syncthreads();
        // store prefetched slab (loaded during previous FFMA burst via a0v/a1v/bv0)
        float4 na0 = Ap0[(k0 >> 2)];
        float4 na1 = Ap1[(k0 >> 2)];
        float4 nb = Bp[(size_t)k0 * 64];   // +k0 rows: k0*256/4? no: rows stride 256 f4
        // Correct B advance: row (k0 + br) -> offset (size_t)k0 * 256 float4
        nb = Bf[(size_t)(k0 + br) * 256 + (col0 >> 2) + bc4];
        As[akq * 4 + 0][ar0] = na0.x; As[akq * 4 + 1][ar0] = na0.y;
        As[akq * 4 + 2][ar0] = na0.z; As[akq * 4 + 3][ar0] = na0.w;
        As[akq * 4 + 0][ar1] = na1.x; As[akq * 4 + 1][ar1] = na1.y;
        As[akq * 4 + 2][ar1] = na1.z; As[akq * 4 + 3][ar1] = na1.w;
        *(float4*)&Bs[br][bc4 * 4] = nb;
        __syncthreads();
    }

    float4 bb = *(const float4*)&bias[col0 + tx * 4];
#pragma unroll
    for (int i = 0; i < 8; i++) {
        int row = row0 + ty * 8 + i;
        float4 o = {acc[i][0] + bb.x, acc[i][1] + bb.y,
                    acc[i][2] + bb.z, acc[i][3] + bb.w};
        *(float4*)&g_C[(size_t)row * DD + col0 + tx * 4] = o;
    }
}

// ---------------- 4) row norms of g_C -> coefK = w / max(norm, eps) ----------------
__global__ __launch_bounds__(256) void norm_kernel() {
    int row = blockIdx.x;  // 0..4095
    int tid = threadIdx.x;
    const float4* c = (const float4*)&g_C[(size_t)row * DD];
    float4 v = c[tid];
    float s = v.x * v.x + v.y * v.y + v.z * v.z + v.w * v.w;
#pragma unroll
    for (int off = 16; off; off >>= 1) s += __shfl_xor_sync(0xFFFFFFFFu, s, off);
    __shared__ float red[8];
    int warp = tid >> 5, lane = tid & 31;
    if (lane == 0) red[warp] = s;
    __syncthreads();
    if (tid == 0) {
        float t = 0.0f;
        for (int i = 0; i < 8; i++) t += red[i];
        g_coefK[row] = g_w[row] / fmaxf(sqrtf(t), 1e-8f);
    }
}

// ---------------- 5) eligK[b,d] = sum_p coefK[b,p] * C[b,p,d] ----------------
__global__ __launch_bounds__(256) void eligk_kernel() {
    int b = blockIdx.x;
    int d = blockIdx.y * 256 + threadIdx.x;
    __shared__ float cs[PP];
    if (threadIdx.x < PP) cs[threadIdx.x] = g_coefK[b * PP + threadIdx.x];
    __syncthreads();
    const float* sp = g_C + (size_t)b * PP * DD + d;
    float acc = 0.0f;
#pragma unroll 8
    for (int p = 0; p < PP; p++) acc += cs[p] * sp[(size_t)p * DD];
    g_eligK[b * DD + d] = acc;
}

// ---------------- 6) eligV[b,:] = hbar[b] @ Wv + wsum[b]*bv  (32x1024x1024) ----------------
__global__ __launch_bounds__(256) void vgemm_kernel(const float* __restrict__ Wv,
                                                    const float* __restrict__ bv) {
    int bg = blockIdx.x;                       // group of 4 batches
    int e = blockIdx.y * 256 + threadIdx.x;
    __shared__ float hs[4][DD];                // 16 KB
    for (int i = threadIdx.x; i < 4 * DD; i += 256)
        hs[i >> 10][i & (DD - 1)] = g_hbar[(size_t)bg * 4 * DD + i];
    __syncthreads();
    float acc0 = 0.f, acc1 = 0.f, acc2 = 0.f, acc3 = 0.f;
#pragma unroll 8
    for (int d = 0; d < DD; d++) {
        float wv = Wv[(size_t)d * DD + e];
        acc0 += hs[0][d] * wv;
        acc1 += hs[1][d] * wv;
        acc2 += hs[2][d] * wv;
        acc3 += hs[3][d] * wv;
    }
    float bve = bv[e];
    g_eligV[(bg * 4 + 0) * DD + e] = acc0 + g_wsum[bg * 4 + 0] * bve;
    g_eligV[(bg * 4 + 1) * DD + e] = acc1 + g_wsum[bg * 4 + 1] * bve;
    g_eligV[(bg * 4 + 2) * DD + e] = acc2 + g_wsum[bg * 4 + 2] * bve;
    g_eligV[(bg * 4 + 3) * DD + e] = acc3 + g_wsum[bg * 4 + 3] * bve;
}

// ---------------- 7) expand to [BS,R,D] outputs ----------------
__global__ __launch_bounds__(256) void expand_kernel(const float* __restrict__ eK0,
                                                     const float* __restrict__ eV0,
                                                     float* __restrict__ outK,
                                                     float* __restrict__ outV) {
    int idx = blockIdx.x * 256 + threadIdx.x;  // over BS*RR*DD
    if (idx >= BS * RR * DD) return;
    int b = idx / (RR * DD);
    int d = idx & (DD - 1);
    float A = g_Atot[b];
    outK[idx] = A * eK0[idx] + g_eligK[b * DD + d];
    outV[idx] = A * eV0[idx] + g_eligV[b * DD + d];
}

// ---------------- 8) readout: y_pm ----------------
__global__ __launch_bounds__(256) void readout_kernel(const float* __restrict__ x,
                                                      const float* __restrict__ pmK,
                                                      const float* __restrict__ pmV,
                                                      const float* __restrict__ pa,
                                                      float* __restrict__ y) {
    extern __shared__ float sm[];
    float* Ks = sm;
    float* Vs = sm + RR * DD;
    __shared__ float pas[RR];
    int b = blockIdx.x;
    int tid = threadIdx.x;

    const float4* Kg = (const float4*)(pmK + (size_t)b * RR * DD);
    const float4* Vg = (const float4*)(pmV + (size_t)b * RR * DD);
    float4* K4 = (float4*)Ks;
    float4* V4 = (float4*)Vs;
    for (int i = tid; i < RR * DD / 4; i += 256) {
        K4[i] = Kg[i];
        V4[i] = Vg[i];
    }
    if (tid < RR) pas[tid] = pa[b * RR + tid];
    __syncthreads();

    int warp = tid >> 5, lane = tid & 31;
    for (int t0 = 0; t0 < 32; t0 += 8) {
        int p = blockIdx.y * 32 + t0 + warp;
        const float4* xr = (const float4*)(x + ((size_t)b * PP + p) * DD);
        float nrm = 0.0f;
        float dot[16];
#pragma unroll
        for (int r = 0; r < 16; r++) dot[r] = 0.0f;
#pragma unroll
        for (int c = 0; c < 8; c++) {
            float4 v = xr[c * 32 + lane];
            nrm += v.x * v.x + v.y * v.y + v.z * v.z + v.w * v.w;
#pragma unroll
            for (int r = 0; r < 16; r++) {
                float4 kv = ((const float4*)(Ks + r * DD))[c * 32 + lane];
                dot[r] += v.x * kv.x + v.y * kv.y + v.z * kv.z + v.w * kv.w;
            }
        }
#pragma unroll
        for (int off = 16; off; off >>= 1) {
            nrm += __shfl_xor_sync(0xFFFFFFFFu, nrm, off);
#pragma unroll
            for (int r = 0; r < 16; r++)
                dot[r] += __shfl_xor_sync(0xFFFFFFFFu, dot[r], off);
        }
        float inv = 1.0f / fmaxf(sqrtf(nrm), 1e-8f);
        float w[16];
#pragma unroll
        for (int r = 0; r < 16; r++) w[r] = pas[r] * dot[r] * inv;

        float4* yo = (float4*)(y + ((size_t)b * PP + p) * DD);
#pragma unroll
        for (int c = 0; c < 8; c++) {
            float4 acc = {0.f, 0.f, 0.f, 0.f};
#pragma unroll
            for (int r = 0; r < 16; r++) {
                float4 vv = ((const float4*)(Vs + r * DD))[c * 32 + lane];
                acc.x += w[r] * vv.x;
                acc.y += w[r] * vv.y;
                acc.z += w[r] * vv.z;
                acc.w += w[r] * vv.w;
            }
            yo[c * 32 + lane] = acc;
        }
    }
}

// ---------------- launch ----------------
extern "C" void kernel_launch(void* const* d_in, const int* in_sizes, int n_in,
                              void* d_out, int out_size) {
    const float* x = (const float*)d_in[0];
    const float* h = (const float*)d_in[1];
    const float* sur = (const float*)d_in[2];
    const unsigned int* mask = (const unsigned int*)d_in[3];  // 0 / nonzero
    const float* pmK = (const float*)d_in[4];
    const float* pmV = (const float*)d_in[5];
    const float* pa = (const float*)d_in[6];
    const float* eK0 = (const float*)d_in[7];
    const float* eV0 = (const float*)d_in[8];
    const float* Wk = (const float*)d_in[9];
    const float* bk = (const float*)d_in[10];
    const float* Wv = (const float*)d_in[11];
    const float* bv = (const float*)d_in[12];

    float* out = (float*)d_out;
    float* y = out;                                  // [BS,P,D]
    float* outK = out + (size_t)BS * PP * DD;        // [BS,R,D]
    float* outV = outK + (size_t)BS * RR * DD;       // [BS,R,D]

    static const int READOUT_SMEM = RR * DD * 2 * (int)sizeof(float);
    cudaFuncSetAttribute(readout_kernel,
                         cudaFuncAttributeMaxDynamicSharedMemorySize, READOUT_SMEM);

    coeff_kernel<<<BS, PP>>>(sur, mask);
    hbar_kernel<<<dim3(BS, DD / 256), 256>>>(h);
    sgemm_kernel<<<dim3(DD / 64, (BS * PP) / 128), 256>>>(x, Wk, bk);
    norm_kernel<<<BS * PP, 256>>>();
    eligk_kernel<<<dim3(BS, DD / 256), 256>>>();
    vgemm_kernel<<<dim3(BS / 4, DD / 256), 256>>>(Wv, bv);
    expand_kernel<<<(BS * RR * DD + 255) / 256, 256>>>(eK0, eV0, outK, outV);
    readout_kernel<<<dim3(BS, PP / 32), 256, READOUT_SMEM>>>(x, pmK, pmV, pa, y);
}

// round 5
// speedup vs baseline: 1.2692x; 1.2692x over previous
#include <cuda_runtime.h>
#include <cuda_bf16.h>
#include <cstdint>

#define BS 32
#define PP 128
#define RR 16
#define DD 1024
#define RHO 0.97f
#define MM (BS * PP)   // 4096 rows of the big GEMM

// ---------------- scratch (no allocations allowed) ----------------
__device__ float g_C[MM * DD];                      // k_cand (fp32, 16 MB)
__device__ __nv_bfloat16 g_A2[(size_t)MM * 2 * DD]; // [4096][2048]: cols 0-1023 hi, 1024-2047 lo
__device__ __nv_bfloat16 g_B2[(size_t)2 * DD * DD]; // [2048][1024]: rows 0-1023 hi, 1024-2047 lo
__device__ float g_normp[MM * 32];                  // per-row sumsq partials (32 col-slots)
__device__ float g_w[MM];                           // w[b,p]
__device__ float g_coefK[MM];                       // w / row_norm
__device__ float g_Atot[BS];
__device__ float g_wsum[BS];
__device__ float g_hbar[BS * DD];
__device__ float g_eligK[BS * DD];
__device__ float g_eligV[BS * DD];

// ---------------- PTX helpers ----------------
__device__ __forceinline__ uint32_t smem_u32(const void* p) {
    return (uint32_t)__cvta_generic_to_shared(p);
}
__device__ __forceinline__ void ldm_x4(uint32_t* r, uint32_t addr) {
    asm volatile("ldmatrix.sync.aligned.m8n8.x4.shared.b16 {%0,%1,%2,%3}, [%4];"
                 : "=r"(r[0]), "=r"(r[1]), "=r"(r[2]), "=r"(r[3]) : "r"(addr));
}
__device__ __forceinline__ void ldm_x4_t(uint32_t& r0, uint32_t& r1, uint32_t& r2,
                                         uint32_t& r3, uint32_t addr) {
    asm volatile("ldmatrix.sync.aligned.m8n8.x4.trans.shared.b16 {%0,%1,%2,%3}, [%4];"
                 : "=r"(r0), "=r"(r1), "=r"(r2), "=r"(r3) : "r"(addr));
}
__device__ __forceinline__ void mma_bf16(float* c, const uint32_t* a, const uint32_t* b) {
    asm volatile("mma.sync.aligned.m16n8k16.row.col.f32.bf16.bf16.f32 "
                 "{%0,%1,%2,%3}, {%4,%5,%6,%7}, {%8,%9}, {%0,%1,%2,%3};"
                 : "+f"(c[0]), "+f"(c[1]), "+f"(c[2]), "+f"(c[3])
                 : "r"(a[0]), "r"(a[1]), "r"(a[2]), "r"(a[3]), "r"(b[0]), "r"(b[1]));
}
__device__ __forceinline__ uint32_t split_pack2(float a, float b, float& ra, float& rb) {
    __nv_bfloat16 ha = __float2bfloat16(a);
    __nv_bfloat16 hb = __float2bfloat16(b);
    ra = a - __bfloat162float(ha);
    rb = b - __bfloat162float(hb);
    __nv_bfloat162 p = __halves2bfloat162(ha, hb);
    return *(uint32_t*)&p;
}
__device__ __forceinline__ uint32_t pack2(float a, float b) {
    __nv_bfloat162 p = __halves2bfloat162(__float2bfloat16(a), __float2bfloat16(b));
    return *(uint32_t*)&p;
}

// ---------------- 1) per-batch coefficients ----------------
__global__ void coeff_kernel(const float* __restrict__ surprise,
                             const unsigned int* __restrict__ mask) {
    int b = blockIdx.x, p = threadIdx.x;  // 128 threads
    __shared__ float a_s[PP], c_s[PP], w_s[PP];
    float g = fminf(fmaxf(surprise[b * PP + p] * 0.2f, 0.0f), 1.0f);
    float a = (mask[b * PP + p] != 0u) ? 0.0f : RHO;
    a_s[p] = a;
    __syncthreads();
    if (p == 0) {
        float c = 1.0f;
        for (int q = PP - 1; q >= 0; --q) { c_s[q] = c; c *= a_s[q]; }
        g_Atot[b] = c;
    }
    __syncthreads();
    float w = g * c_s[p];
    w_s[p] = w;
    g_w[b * PP + p] = w;
    __syncthreads();
    if (p == 0) {
        float s = 0.0f;
        for (int q = 0; q < PP; q++) s += w_s[q];
        g_wsum[b] = s;
    }
}

// ---------------- 2) bf16 hi/lo split conversions ----------------
__global__ __launch_bounds__(256) void convA_kernel(const float* __restrict__ x) {
    int i4 = blockIdx.x * 256 + threadIdx.x;  // over MM*DD/4 float4s
    float4 v = ((const float4*)x)[i4];
    int row = i4 >> 8;            // 256 float4 per row
    int c4 = i4 & 255;
    float rx, ry, rz, rw;
    uint32_t h0 = split_pack2(v.x, v.y, rx, ry);
    uint32_t h1 = split_pack2(v.z, v.w, rz, rw);
    uint32_t l0 = pack2(rx, ry);
    uint32_t l1 = pack2(rz, rw);
    uint2* dhi = (uint2*)&g_A2[(size_t)row * 2048 + c4 * 4];
    uint2* dlo = (uint2*)&g_A2[(size_t)row * 2048 + 1024 + c4 * 4];
    *dhi = make_uint2(h0, h1);
    *dlo = make_uint2(l0, l1);
}

__global__ __launch_bounds__(256) void convB_kernel(const float* __restrict__ Wk) {
    int i4 = blockIdx.x * 256 + threadIdx.x;  // over DD*DD/4
    float4 v = ((const float4*)Wk)[i4];
    int row = i4 >> 8;
    int c4 = i4 & 255;
    float rx, ry, rz, rw;
    uint32_t h0 = split_pack2(v.x, v.y, rx, ry);
    uint32_t h1 = split_pack2(v.z, v.w, rz, rw);
    uint32_t l0 = pack2(rx, ry);
    uint32_t l1 = pack2(rz, rw);
    uint2* dhi = (uint2*)&g_B2[(size_t)row * 1024 + c4 * 4];
    uint2* dlo = (uint2*)&g_B2[(size_t)(row + 1024) * 1024 + c4 * 4];
    *dhi = make_uint2(h0, h1);
    *dlo = make_uint2(l0, l1);
}

// ---------------- 3) hbar[b,d] = sum_p w[b,p] * h[b,p,d] ----------------
__global__ __launch_bounds__(256) void hbar_kernel(const float* __restrict__ h) {
    int b = blockIdx.x;
    int d = blockIdx.y * 256 + threadIdx.x;
    __shared__ float cs[PP];
    if (threadIdx.x < PP) cs[threadIdx.x] = g_w[b * PP + threadIdx.x];
    __syncthreads();
    const float* sp = h + (size_t)b * PP * DD + d;
    float acc = 0.0f;
#pragma unroll 8
    for (int p = 0; p < PP; p++) acc += cs[p] * sp[(size_t)p * DD];
    g_hbar[b * DD + d] = acc;
}

// ---------------- 4) tensor-core GEMM: C = X @ Wk + bk via bf16 split ----------------
// Effective K = 3 segments x 1024: (Ahi,Bhi), (Ahi,Blo), (Alo,Bhi).
// Block 128x128, BK=32, 8 warps (2x4), per warp 64x32 = 4x4 m16n8 tiles.
#define GBM 128
#define GBN 128
#define AST 40    // A smem row stride in halfs (32 + 8 pad)
#define BST 136   // B smem row stride in halfs (128 + 8 pad)

__global__ __launch_bounds__(256) void mma_gemm_kernel(const float* __restrict__ bias) {
    __shared__ __align__(16) __nv_bfloat16 As[2][GBM * AST];    // 20 KB
    __shared__ __align__(16) __nv_bfloat16 Bsm[2][32 * BST];    // 17 KB
    int tid = threadIdx.x;
    int lane = tid & 31, warp = tid >> 5;
    int wm = warp >> 2, wn = warp & 3;
    int bm = blockIdx.y * GBM, bn = blockIdx.x * GBN;

    float acc[4][4][4];
#pragma unroll
    for (int i = 0; i < 4; i++)
#pragma unroll
        for (int j = 0; j < 4; j++)
#pragma unroll
            for (int k = 0; k < 4; k++) acc[i][j][k] = 0.0f;

    // global load geometry: A 2 uint4/thread (row tid>>1), B 2 uint4/thread (row tid>>3)
    int arow = tid >> 1;
    int acol = (tid & 1) * 16;        // halfs
    int brow = tid >> 3;
    int bcol = (tid & 7) * 16;

    const __nv_bfloat16* Abase = g_A2 + (size_t)(bm + arow) * 2048 + acol;
    uint4 ra0, ra1, rb0, rb1;

    // ldmatrix per-thread offsets
    int g8 = lane >> 3;               // matrix index 0..3
    int r8 = lane & 7;
    int aRowOff = wm * 64 + r8 + (g8 & 1) * 8;   // + tm*16
    int aColOff = (g8 >> 1) * 8;                 // + ks
    int bRowOff = r8 + (g8 & 1) * 8;             // + ks
    int bColOff = wn * 32 + (g8 >> 1) * 8;       // + tp*16

    // ---- load tile i into regs ----
#define LOAD_TILE(i)                                                               \
    {                                                                              \
        int s_ = (i) >> 5;                                                         \
        int kt_ = (i) & 31;                                                        \
        int aoff_ = (s_ == 2) ? 1024 : 0;                                          \
        int boff_ = (s_ == 1) ? 1024 : 0;                                          \
        const uint4* pa_ = (const uint4*)(Abase + aoff_ + kt_ * 32);               \
        ra0 = pa_[0]; ra1 = pa_[1];                                                \
        const uint4* pb_ = (const uint4*)(g_B2 +                                   \
            (size_t)(boff_ + kt_ * 32 + brow) * 1024 + bn + bcol);                 \
        rb0 = pb_[0]; rb1 = pb_[1];                                                \
    }
#define STORE_TILE(buf)                                                            \
    {                                                                              \
        uint4* da_ = (uint4*)&As[buf][arow * AST + acol];                          \
        da_[0] = ra0; da_[1] = ra1;                                                \
        uint4* db_ = (uint4*)&Bsm[buf][brow * BST + bcol];                         \
        db_[0] = rb0; db_[1] = rb1;                                                \
    }

    LOAD_TILE(0);
    STORE_TILE(0);
    __syncthreads();

    int buf = 0;
    for (int i = 0; i < 96; i++) {
        if (i < 95) LOAD_TILE(i + 1);
        // compute 2 x k16 from smem[buf]
#pragma unroll
        for (int ks = 0; ks < 32; ks += 16) {
            uint32_t afr[4][4], bfr[4][2];
#pragma unroll
            for (int tm = 0; tm < 4; tm++) {
                uint32_t addr = smem_u32(&As[buf][(aRowOff + tm * 16) * AST + aColOff + ks]);
                ldm_x4(afr[tm], addr);
            }
#pragma unroll
            for (int tp = 0; tp < 2; tp++) {
                uint32_t r0, r1, r2, r3;
                uint32_t addr = smem_u32(&Bsm[buf][(bRowOff + ks) * BST + bColOff + tp * 16]);
                ldm_x4_t(r0, r1, r2, r3, addr);
                bfr[tp * 2][0] = r0; bfr[tp * 2][1] = r1;
                bfr[tp * 2 + 1][0] = r2; bfr[tp * 2 + 1][1] = r3;
            }
#pragma unroll
            for (int tm = 0; tm < 4; tm++)
#pragma unroll
                for (int tn = 0; tn < 4; tn++)
                    mma_bf16(acc[tm][tn], afr[tm], bfr[tn]);
        }
        if (i < 95) {
            STORE_TILE(buf ^ 1);
            __syncthreads();
            buf ^= 1;
        }
    }

    // ---- epilogue: bias add, fp32 store, deterministic sumsq partials ----
    int gq = lane >> 2;   // row-in-8
    int cq = lane & 3;    // col pair
#pragma unroll
    for (int tm = 0; tm < 4; tm++) {
        int row0 = bm + wm * 64 + tm * 16 + gq;
        float s0 = 0.0f, s1 = 0.0f;
#pragma unroll
        for (int tn = 0; tn < 4; tn++) {
            int col = bn + wn * 32 + tn * 8 + cq * 2;
            float2 bb = *(const float2*)&bias[col];
            float v0 = acc[tm][tn][0] + bb.x;
            float v1 = acc[tm][tn][1] + bb.y;
            float v2 = acc[tm][tn][2] + bb.x;
            float v3 = acc[tm][tn][3] + bb.y;
            *(float2*)&g_C[(size_t)row0 * DD + col] = make_float2(v0, v1);
            *(float2*)&g_C[(size_t)(row0 + 8) * DD + col] = make_float2(v2, v3);
            s0 += v0 * v0 + v1 * v1;
            s1 += v2 * v2 + v3 * v3;
        }
        s0 += __shfl_xor_sync(0xFFFFFFFFu, s0, 1);
        s0 += __shfl_xor_sync(0xFFFFFFFFu, s0, 2);
        s1 += __shfl_xor_sync(0xFFFFFFFFu, s1, 1);
        s1 += __shfl_xor_sync(0xFFFFFFFFu, s1, 2);
        if (cq == 0) {
            int slot = blockIdx.x * 4 + wn;
            g_normp[(size_t)row0 * 32 + slot] = s0;
            g_normp[(size_t)(row0 + 8) * 32 + slot] = s1;
        }
    }
#undef LOAD_TILE
#undef STORE_TILE
}

// ---------------- 5) coefK = w / max(norm, eps) ----------------
__global__ __launch_bounds__(256) void coefk_kernel() {
    int row = blockIdx.x * 256 + threadIdx.x;  // 4096
    const float* p = &g_normp[row * 32];
    float s = 0.0f;
#pragma unroll
    for (int i = 0; i < 32; i++) s += p[i];
    g_coefK[row] = g_w[row] / fmaxf(sqrtf(s), 1e-8f);
}

// ---------------- 6) eligK[b,d] = sum_p coefK[b,p] * C[b,p,d] ----------------
__global__ __launch_bounds__(256) void eligk_kernel() {
    int b = blockIdx.x;
    int d = blockIdx.y * 256 + threadIdx.x;
    __shared__ float cs[PP];
    if (threadIdx.x < PP) cs[threadIdx.x] = g_coefK[b * PP + threadIdx.x];
    __syncthreads();
    const float* sp = g_C + (size_t)b * PP * DD + d;
    float acc = 0.0f;
#pragma unroll 8
    for (int p = 0; p < PP; p++) acc += cs[p] * sp[(size_t)p * DD];
    g_eligK[b * DD + d] = acc;
}

// ---------------- 7) eligV[b,:] = hbar[b] @ Wv + wsum[b]*bv ----------------
__global__ __launch_bounds__(256) void vgemm_kernel(const float* __restrict__ Wv,
                                                    const float* __restrict__ bv) {
    int bg = blockIdx.x;
    int e = blockIdx.y * 256 + threadIdx.x;
    __shared__ float hs[4][DD];
    for (int i = threadIdx.x; i < 4 * DD; i += 256)
        hs[i >> 10][i & (DD - 1)] = g_hbar[(size_t)bg * 4 * DD + i];
    __syncthreads();
    float acc0 = 0.f, acc1 = 0.f, acc2 = 0.f, acc3 = 0.f;
#pragma unroll 8
    for (int d = 0; d < DD; d++) {
        float wv = Wv[(size_t)d * DD + e];
        acc0 += hs[0][d] * wv;
        acc1 += hs[1][d] * wv;
        acc2 += hs[2][d] * wv;
        acc3 += hs[3][d] * wv;
    }
    float bve = bv[e];
    g_eligV[(bg * 4 + 0) * DD + e] = acc0 + g_wsum[bg * 4 + 0] * bve;
    g_eligV[(bg * 4 + 1) * DD + e] = acc1 + g_wsum[bg * 4 + 1] * bve;
    g_eligV[(bg * 4 + 2) * DD + e] = acc2 + g_wsum[bg * 4 + 2] * bve;
    g_eligV[(bg * 4 + 3) * DD + e] = acc3 + g_wsum[bg * 4 + 3] * bve;
}

// ---------------- 8) expand to [BS,R,D] outputs ----------------
__global__ __launch_bounds__(256) void expand_kernel(const float* __restrict__ eK0,
                                                     const float* __restrict__ eV0,
                                                     float* __restrict__ outK,
                                                     float* __restrict__ outV) {
    int idx = blockIdx.x * 256 + threadIdx.x;
    if (idx >= BS * RR * DD) return;
    int b = idx / (RR * DD);
    int d = idx & (DD - 1);
    float A = g_Atot[b];
    outK[idx] = A * eK0[idx] + g_eligK[b * DD + d];
    outV[idx] = A * eV0[idx] + g_eligV[b * DD + d];
}

// ---------------- 9) readout: y_pm ----------------
__global__ __launch_bounds__(256) void readout_kernel(const float* __restrict__ x,
                                                      const float* __restrict__ pmK,
                                                      const float* __restrict__ pmV,
                                                      const float* __restrict__ pa,
                                                      float* __restrict__ y) {
    extern __shared__ float sm[];
    float* Ks = sm;
    float* Vs = sm + RR * DD;
    __shared__ float pas[RR];
    int b = blockIdx.x;
    int tid = threadIdx.x;

    const float4* Kg = (const float4*)(pmK + (size_t)b * RR * DD);
    const float4* Vg = (const float4*)(pmV + (size_t)b * RR * DD);
    float4* K4 = (float4*)Ks;
    float4* V4 = (float4*)Vs;
    for (int i = tid; i < RR * DD / 4; i += 256) {
        K4[i] = Kg[i];
        V4[i] = Vg[i];
    }
    if (tid < RR) pas[tid] = pa[b * RR + tid];
    __syncthreads();

    int warp = tid >> 5, lane = tid & 31;
    for (int t0 = 0; t0 < 32; t0 += 8) {
        int p = blockIdx.y * 32 + t0 + warp;
        const float4* xr = (const float4*)(x + ((size_t)b * PP + p) * DD);
        float nrm = 0.0f;
        float dot[16];
#pragma unroll
        for (int r = 0; r < 16; r++) dot[r] = 0.0f;
#pragma unroll
        for (int c = 0; c < 8; c++) {
            float4 v = xr[c * 32 + lane];
            nrm += v.x * v.x + v.y * v.y + v.z * v.z + v.w * v.w;
#pragma unroll
            for (int r = 0; r < 16; r++) {
                float4 kv = ((const float4*)(Ks + r * DD))[c * 32 + lane];
                dot[r] += v.x * kv.x + v.y * kv.y + v.z * kv.z + v.w * kv.w;
            }
        }
#pragma unroll
        for (int off = 16; off; off >>= 1) {
            nrm += __shfl_xor_sync(0xFFFFFFFFu, nrm, off);
#pragma unroll
            for (int r = 0; r < 16; r++)
                dot[r] += __shfl_xor_sync(0xFFFFFFFFu, dot[r], off);
        }
        float inv = 1.0f / fmaxf(sqrtf(nrm), 1e-8f);
        float w[16];
#pragma unroll
        for (int r = 0; r < 16; r++) w[r] = pas[r] * dot[r] * inv;

        float4* yo = (float4*)(y + ((size_t)b * PP + p) * DD);
#pragma unroll
        for (int c = 0; c < 8; c++) {
            float4 acc = {0.f, 0.f, 0.f, 0.f};
#pragma unroll
            for (int r = 0; r < 16; r++) {
                float4 vv = ((const float4*)(Vs + r * DD))[c * 32 + lane];
                acc.x += w[r] * vv.x;
                acc.y += w[r] * vv.y;
                acc.z += w[r] * vv.z;
                acc.w += w[r] * vv.w;
            }
            yo[c * 32 + lane] = acc;
        }
    }
}

// ---------------- launch ----------------
extern "C" void kernel_launch(void* const* d_in, const int* in_sizes, int n_in,
                              void* d_out, int out_size) {
    const float* x = (const float*)d_in[0];
    const float* h = (const float*)d_in[1];
    const float* sur = (const float*)d_in[2];
    const unsigned int* mask = (const unsigned int*)d_in[3];
    const float* pmK = (const float*)d_in[4];
    const float* pmV = (const float*)d_in[5];
    const float* pa = (const float*)d_in[6];
    const float* eK0 = (const float*)d_in[7];
    const float* eV0 = (const float*)d_in[8];
    const float* Wk = (const float*)d_in[9];
    const float* bk = (const float*)d_in[10];
    const float* Wv = (const float*)d_in[11];
    const float* bv = (const float*)d_in[12];

    float* out = (float*)d_out;
    float* y = out;
    float* outK = out + (size_t)BS * PP * DD;
    float* outV = outK + (size_t)BS * RR * DD;

    static const int READOUT_SMEM = RR * DD * 2 * (int)sizeof(float);
    cudaFuncSetAttribute(readout_kernel,
                         cudaFuncAttributeMaxDynamicSharedMemorySize, READOUT_SMEM);

    coeff_kernel<<<BS, PP>>>(sur, mask);
    convA_kernel<<<MM * DD / 4 / 256, 256>>>(x);
    convB_kernel<<<DD * DD / 4 / 256, 256>>>(Wk);
    hbar_kernel<<<dim3(BS, DD / 256), 256>>>(h);
    mma_gemm_kernel<<<dim3(DD / GBN, MM / GBM), 256>>>(bk);
    coefk_kernel<<<MM / 256, 256>>>();
    eligk_kernel<<<dim3(BS, DD / 256), 256>>>();
    vgemm_kernel<<<dim3(BS / 4, DD / 256), 256>>>(Wv, bv);
    expand_kernel<<<(BS * RR * DD + 255) / 256, 256>>>(eK0, eV0, outK, outV);
    readout_kernel<<<dim3(BS, PP / 32), 256, READOUT_SMEM>>>(x, pmK, pmV, pa, y);
}

// round 7
// speedup vs baseline: 1.3534x; 1.0663x over previous
#include <cuda_runtime.h>
#include <cuda_bf16.h>
#include <cstdint>

#define BS 32
#define PP 128
#define RR 16
#define DD 1024
#define RHO 0.97f
#define MM (BS * PP)   // 4096 rows of the big GEMM

// ---------------- scratch (no allocations allowed) ----------------
__device__ float g_C[MM * DD];                       // k_cand (fp32, 16 MB)
__device__ __nv_bfloat16 g_A2[(size_t)MM * 2 * DD];  // [4096][2048]: cols 0-1023 hi, 1024-2047 lo
__device__ __nv_bfloat16 g_B2[(size_t)2 * DD * DD];  // [2048 k][1024 n]: rows 0-1023 hi, 1024-2047 lo
__device__ float g_normp[MM * 32];                   // per-row sumsq partials (8 Nblk x 4 warps)
__device__ float g_w[MM];
__device__ float g_coefK[MM];
__device__ float g_Atot[BS];
__device__ float g_wsum[BS];
__device__ float g_hbarp[4 * BS * DD];               // p-split partials
__device__ float g_eligKp[4 * BS * DD];              // p-split partials
__device__ float g_eligV[BS * DD];

// ---------------- PTX helpers ----------------
__device__ __forceinline__ uint32_t smem_u32(const void* p) {
    return (uint32_t)__cvta_generic_to_shared(p);
}
__device__ __forceinline__ void cp_async16(uint32_t dst, const void* src) {
    asm volatile("cp.async.cg.shared.global [%0], [%1], 16;" :: "r"(dst), "l"(src));
}
#define CP_COMMIT() asm volatile("cp.async.commit_group;" ::: "memory")
#define CP_WAIT2()  asm volatile("cp.async.wait_group 2;" ::: "memory")
#define CP_WAIT0()  asm volatile("cp.async.wait_group 0;" ::: "memory")

__device__ __forceinline__ void ldm_x4(uint32_t* r, uint32_t addr) {
    asm volatile("ldmatrix.sync.aligned.m8n8.x4.shared.b16 {%0,%1,%2,%3}, [%4];"
                 : "=r"(r[0]), "=r"(r[1]), "=r"(r[2]), "=r"(r[3]) : "r"(addr));
}
__device__ __forceinline__ void ldm_x4_t(uint32_t& r0, uint32_t& r1, uint32_t& r2,
                                         uint32_t& r3, uint32_t addr) {
    asm volatile("ldmatrix.sync.aligned.m8n8.x4.trans.shared.b16 {%0,%1,%2,%3}, [%4];"
                 : "=r"(r0), "=r"(r1), "=r"(r2), "=r"(r3) : "r"(addr));
}
__device__ __forceinline__ void mma_bf16(float* c, const uint32_t* a, const uint32_t* b) {
    asm volatile("mma.sync.aligned.m16n8k16.row.col.f32.bf16.bf16.f32 "
                 "{%0,%1,%2,%3}, {%4,%5,%6,%7}, {%8,%9}, {%0,%1,%2,%3};"
                 : "+f"(c[0]), "+f"(c[1]), "+f"(c[2]), "+f"(c[3])
                 : "r"(a[0]), "r"(a[1]), "r"(a[2]), "r"(a[3]), "r"(b[0]), "r"(b[1]));
}
__device__ __forceinline__ uint32_t split_pack2(float a, float b, float& ra, float& rb) {
    __nv_bfloat16 ha = __float2bfloat16(a);
    __nv_bfloat16 hb = __float2bfloat16(b);
    ra = a - __bfloat162float(ha);
    rb = b - __bfloat162float(hb);
    __nv_bfloat162 p = __halves2bfloat162(ha, hb);
    return *(uint32_t*)&p;
}
__device__ __forceinline__ uint32_t pack2(float a, float b) {
    __nv_bfloat162 p = __halves2bfloat162(__float2bfloat16(a), __float2bfloat16(b));
    return *(uint32_t*)&p;
}

// ---------------- 1) per-batch coefficients ----------------
__global__ void coeff_kernel(const float* __restrict__ surprise,
                             const unsigned int* __restrict__ mask) {
    int b = blockIdx.x, p = threadIdx.x;  // 128 threads
    __shared__ float a_s[PP], c_s[PP], w_s[PP];
    float g = fminf(fmaxf(surprise[b * PP + p] * 0.2f, 0.0f), 1.0f);
    float a = (mask[b * PP + p] != 0u) ? 0.0f : RHO;
    a_s[p] = a;
    __syncthreads();
    if (p == 0) {
        float c = 1.0f;
        for (int q = PP - 1; q >= 0; --q) { c_s[q] = c; c *= a_s[q]; }
        g_Atot[b] = c;
    }
    __syncthreads();
    float w = g * c_s[p];
    w_s[p] = w;
    g_w[b * PP + p] = w;
    __syncthreads();
    if (p == 0) {
        float s = 0.0f;
        for (int q = 0; q < PP; q++) s += w_s[q];
        g_wsum[b] = s;
    }
}

// ---------------- 2a) A hi/lo split ----------------
__global__ __launch_bounds__(256) void convA_kernel(const float* __restrict__ x) {
    int i4 = blockIdx.x * 256 + threadIdx.x;  // over MM*DD/4 float4s
    float4 v = ((const float4*)x)[i4];
    int row = i4 >> 8;
    int c4 = i4 & 255;
    float rx, ry, rz, rw;
    uint32_t h0 = split_pack2(v.x, v.y, rx, ry);
    uint32_t h1 = split_pack2(v.z, v.w, rz, rw);
    uint32_t l0 = pack2(rx, ry);
    uint32_t l1 = pack2(rz, rw);
    *(uint2*)&g_A2[(size_t)row * 2048 + c4 * 4] = make_uint2(h0, h1);
    *(uint2*)&g_A2[(size_t)row * 2048 + 1024 + c4 * 4] = make_uint2(l0, l1);
}

// ---------------- 2b) B hi/lo split (keeps [K][N] layout) ----------------
__global__ __launch_bounds__(256) void convB_kernel(const float* __restrict__ Wk) {
    int i4 = blockIdx.x * 256 + threadIdx.x;  // over DD*DD/4
    float4 v = ((const float4*)Wk)[i4];
    int row = i4 >> 8;
    int c4 = i4 & 255;
    float rx, ry, rz, rw;
    uint32_t h0 = split_pack2(v.x, v.y, rx, ry);
    uint32_t h1 = split_pack2(v.z, v.w, rz, rw);
    uint32_t l0 = pack2(rx, ry);
    uint32_t l1 = pack2(rz, rw);
    *(uint2*)&g_B2[(size_t)row * 1024 + c4 * 4] = make_uint2(h0, h1);
    *(uint2*)&g_B2[(size_t)(row + 1024) * 1024 + c4 * 4] = make_uint2(l0, l1);
}

// ---------------- 3) hbar partials: grid (BS, 4, 4) ----------------
__global__ __launch_bounds__(256) void hbar_kernel(const float* __restrict__ h) {
    int b = blockIdx.x, s = blockIdx.z;
    int d = blockIdx.y * 256 + threadIdx.x;
    __shared__ float cs[32];
    if (threadIdx.x < 32) cs[threadIdx.x] = g_w[b * PP + s * 32 + threadIdx.x];
    __syncthreads();
    const float* sp = h + ((size_t)b * PP + s * 32) * DD + d;
    float acc = 0.0f;
#pragma unroll
    for (int p = 0; p < 32; p++) acc += cs[p] * sp[(size_t)p * DD];
    g_hbarp[((s * BS + b) << 10) + d] = acc;
}

// ---------------- 4) mma.sync GEMM with 4-stage cp.async pipeline ----------------
// C = X @ Wk + bk, bf16 3-term split (eff. 96 K-tiles of 32).
// Block 128x128, 8 warps (2x4), warp tile 64x32 = 4x4 m16n8k16.
// smem per stage: A 128x(32+8 pad) halfs = 10240 B, B 32x(128+8) halfs = 8704 B.
#define ASTB 80       // A smem row stride bytes
#define BSTB 272      // B smem row stride bytes
#define ASTG_A 10240
#define STAGE_B 18944
#define NSTAGE 4
#define GSMEM (NSTAGE * STAGE_B)   // 75776 B

__global__ __launch_bounds__(256) void mma_gemm_kernel(const float* __restrict__ bias) {
    extern __shared__ char smem[];
    uint32_t sb = smem_u32(smem);
    int tid = threadIdx.x;
    int lane = tid & 31, warp = tid >> 5;
    int wm = warp >> 2, wn = warp & 3;
    int bm = blockIdx.y * 128, bn = blockIdx.x * 128;

    float acc[4][4][4];
#pragma unroll
    for (int i = 0; i < 4; i++)
#pragma unroll
        for (int j = 0; j < 4; j++)
#pragma unroll
            for (int k = 0; k < 4; k++) acc[i][j][k] = 0.0f;

    // cp.async geometry: A 512 chunks (row=id>>2, ch=id&3), B 512 (row=id>>4, ch=id&15)
    int aid0 = tid * 2;
    int arow0 = aid0 >> 2, ach0 = aid0 & 3;
    int arow1 = (aid0 + 1) >> 2, ach1 = (aid0 + 1) & 3;
    int brow0 = aid0 >> 4, bch0 = aid0 & 15;
    int brow1 = (aid0 + 1) >> 4, bch1 = (aid0 + 1) & 15;

    auto issue_stage = [&](int i, int slot) {
        int seg = i >> 5, kt = i & 31;
        int ak = ((seg == 2) ? 1024 : 0) + kt * 32;
        int bk = ((seg == 1) ? 1024 : 0) + kt * 32;
        uint32_t sA = sb + slot * STAGE_B;
        uint32_t sB = sA + ASTG_A;
        cp_async16(sA + arow0 * ASTB + ach0 * 16,
                   &g_A2[(size_t)(bm + arow0) * 2048 + ak + ach0 * 8]);
        cp_async16(sA + arow1 * ASTB + ach1 * 16,
                   &g_A2[(size_t)(bm + arow1) * 2048 + ak + ach1 * 8]);
        cp_async16(sB + brow0 * BSTB + bch0 * 16,
                   &g_B2[(size_t)(bk + brow0) * 1024 + bn + bch0 * 8]);
        cp_async16(sB + brow1 * BSTB + bch1 * 16,
                   &g_B2[(size_t)(bk + brow1) * 1024 + bn + bch1 * 8]);
    };

    // ldmatrix per-thread offsets (bytes)
    int g8 = lane >> 3;
    int r8 = lane & 7;
    int aRowOff = wm * 64 + r8 + (g8 & 1) * 8;   // + tm*16
    int aColB = (g8 >> 1) * 16;                  // + ks*2
    int bRowOff = r8 + (g8 & 1) * 8;             // + ks
    int bColB = (wn * 32 + (g8 >> 1) * 8) * 2;   // + tp*32

    // prologue: stages 0..2
#pragma unroll
    for (int i = 0; i < NSTAGE - 1; i++) {
        issue_stage(i, i);
        CP_COMMIT();
    }

    for (int i = 0; i < 96; i++) {
        CP_WAIT2();
        __syncthreads();
        int slot = i & (NSTAGE - 1);
        uint32_t sA = sb + slot * STAGE_B;
        uint32_t sB = sA + ASTG_A;
#pragma unroll
        for (int ks = 0; ks < 32; ks += 16) {
            uint32_t afr[4][4], bfr[4][2];
#pragma unroll
            for (int tm = 0; tm < 4; tm++)
                ldm_x4(afr[tm], sA + (aRowOff + tm * 16) * ASTB + aColB + ks * 2);
#pragma unroll
            for (int tp = 0; tp < 2; tp++) {
                uint32_t r0, r1, r2, r3;
                ldm_x4_t(r0, r1, r2, r3,
                         sB + (bRowOff + ks) * BSTB + bColB + tp * 32);
                bfr[tp * 2][0] = r0; bfr[tp * 2][1] = r1;
                bfr[tp * 2 + 1][0] = r2; bfr[tp * 2 + 1][1] = r3;
            }
#pragma unroll
            for (int tm = 0; tm < 4; tm++)
#pragma unroll
                for (int tn = 0; tn < 4; tn++)
                    mma_bf16(acc[tm][tn], afr[tm], bfr[tn]);
        }
        if (i + NSTAGE - 1 < 96) issue_stage(i + NSTAGE - 1, (i + NSTAGE - 1) & (NSTAGE - 1));
        CP_COMMIT();
    }
    CP_WAIT0();

    // ---- epilogue: bias add, fp32 store, deterministic sumsq partials ----
    int gq = lane >> 2;   // row-in-8
    int cq = lane & 3;    // col pair
#pragma unroll
    for (int tm = 0; tm < 4; tm++) {
        int row0 = bm + wm * 64 + tm * 16 + gq;
        float s0 = 0.0f, s1 = 0.0f;
#pragma unroll
        for (int tn = 0; tn < 4; tn++) {
            int col = bn + wn * 32 + tn * 8 + cq * 2;
            float2 bb = *(const float2*)&bias[col];
            float v0 = acc[tm][tn][0] + bb.x;
            float v1 = acc[tm][tn][1] + bb.y;
            float v2 = acc[tm][tn][2] + bb.x;
            float v3 = acc[tm][tn][3] + bb.y;
            *(float2*)&g_C[(size_t)row0 * DD + col] = make_float2(v0, v1);
            *(float2*)&g_C[(size_t)(row0 + 8) * DD + col] = make_float2(v2, v3);
            s0 += v0 * v0 + v1 * v1;
            s1 += v2 * v2 + v3 * v3;
        }
        s0 += __shfl_xor_sync(0xFFFFFFFFu, s0, 1);
        s0 += __shfl_xor_sync(0xFFFFFFFFu, s0, 2);
        s1 += __shfl_xor_sync(0xFFFFFFFFu, s1, 1);
        s1 += __shfl_xor_sync(0xFFFFFFFFu, s1, 2);
        if (cq == 0) {
            int slot = blockIdx.x * 4 + wn;
            g_normp[(size_t)row0 * 32 + slot] = s0;
            g_normp[(size_t)(row0 + 8) * 32 + slot] = s1;
        }
    }
}

// ---------------- 5) coefK = w / max(norm, eps) ----------------
__global__ __launch_bounds__(256) void coefk_kernel() {
    int row = blockIdx.x * 256 + threadIdx.x;  // 4096
    const float* p = &g_normp[row * 32];
    float s = 0.0f;
#pragma unroll
    for (int i = 0; i < 32; i++) s += p[i];
    g_coefK[row] = g_w[row] / fmaxf(sqrtf(s), 1e-8f);
}

// ---------------- 6) eligK partials: grid (BS, 4, 4) ----------------
__global__ __launch_bounds__(256) void eligk_kernel() {
    int b = blockIdx.x, s = blockIdx.z;
    int d = blockIdx.y * 256 + threadIdx.x;
    __shared__ float cs[32];
    if (threadIdx.x < 32) cs[threadIdx.x] = g_coefK[b * PP + s * 32 + threadIdx.x];
    __syncthreads();
    const float* sp = g_C + ((size_t)b * PP + s * 32) * DD + d;
    float acc = 0.0f;
#pragma unroll
    for (int p = 0; p < 32; p++) acc += cs[p] * sp[(size_t)p * DD];
    g_eligKp[((s * BS + b) << 10) + d] = acc;
}

// ---------------- 7) eligV[b,:] = hbar[b] @ Wv + wsum[b]*bv ----------------
__global__ __launch_bounds__(256) void vgemm_kernel(const float* __restrict__ Wv,
                                                    const float* __restrict__ bv) {
    int bg = blockIdx.x;
    int e = blockIdx.y * 256 + threadIdx.x;
    __shared__ float hs[4][DD];
    for (int i = threadIdx.x; i < 4 * DD; i += 256) {
        int bl = i >> 10, d = i & 1023;
        int b = bg * 4 + bl;
        float v = 0.0f;
#pragma unroll
        for (int s = 0; s < 4; s++) v += g_hbarp[((s * BS + b) << 10) + d];
        hs[bl][d] = v;
    }
    __syncthreads();
    float acc0 = 0.f, acc1 = 0.f, acc2 = 0.f, acc3 = 0.f;
#pragma unroll 8
    for (int d = 0; d < DD; d++) {
        float wv = Wv[(size_t)d * DD + e];
        acc0 += hs[0][d] * wv;
        acc1 += hs[1][d] * wv;
        acc2 += hs[2][d] * wv;
        acc3 += hs[3][d] * wv;
    }
    float bve = bv[e];
    g_eligV[(bg * 4 + 0) * DD + e] = acc0 + g_wsum[bg * 4 + 0] * bve;
    g_eligV[(bg * 4 + 1) * DD + e] = acc1 + g_wsum[bg * 4 + 1] * bve;
    g_eligV[(bg * 4 + 2) * DD + e] = acc2 + g_wsum[bg * 4 + 2] * bve;
    g_eligV[(bg * 4 + 3) * DD + e] = acc3 + g_wsum[bg * 4 + 3] * bve;
}

// ---------------- 8) expand to [BS,R,D] outputs ----------------
__global__ __launch_bounds__(256) void expand_kernel(const float* __restrict__ eK0,
                                                     const float* __restrict__ eV0,
                                                     float* __restrict__ outK,
                                                     float* __restrict__ outV) {
    int idx = blockIdx.x * 256 + threadIdx.x;
    if (idx >= BS * RR * DD) return;
    int b = idx / (RR * DD);
    int d = idx & (DD - 1);
    float A = g_Atot[b];
    float ek = 0.0f;
#pragma unroll
    for (int s = 0; s < 4; s++) ek += g_eligKp[((s * BS + b) << 10) + d];
    outK[idx] = A * eK0[idx] + ek;
    outV[idx] = A * eV0[idx] + g_eligV[b * DD + d];
}

// ---------------- 9) readout: y_pm ----------------
__global__ __launch_bounds__(256) void readout_kernel(const float* __restrict__ x,
                                                      const float* __restrict__ pmK,
                                                      const float* __restrict__ pmV,
                                                      const float* __restrict__ pa,
                                                      float* __restrict__ y) {
    extern __shared__ float sm[];
    float* Ks = sm;
    float* Vs = sm + RR * DD;
    __shared__ float pas[RR];
    int b = blockIdx.x;
    int tid = threadIdx.x;

    const float4* Kg = (const float4*)(pmK + (size_t)b * RR * DD);
    const float4* Vg = (const float4*)(pmV + (size_t)b * RR * DD);
    float4* K4 = (float4*)Ks;
    float4* V4 = (float4*)Vs;
    for (int i = tid; i < RR * DD / 4; i += 256) {
        K4[i] = Kg[i];
        V4[i] = Vg[i];
    }
    if (tid < RR) pas[tid] = pa[b * RR + tid];
    __syncthreads();

    int warp = tid >> 5, lane = tid & 31;
    for (int t0 = 0; t0 < 32; t0 += 8) {
        int p = blockIdx.y * 32 + t0 + warp;
        const float4* xr = (const float4*)(x + ((size_t)b * PP + p) * DD);
        float nrm = 0.0f;
        float dot[16];
#pragma unroll
        for (int r = 0; r < 16; r++) dot[r] = 0.0f;
#pragma unroll
        for (int c = 0; c < 8; c++) {
            float4 v = xr[c * 32 + lane];
            nrm += v.x * v.x + v.y * v.y + v.z * v.z + v.w * v.w;
#pragma unroll
            for (int r = 0; r < 16; r++) {
                float4 kv = ((const float4*)(Ks + r * DD))[c * 32 + lane];
                dot[r] += v.x * kv.x + v.y * kv.y + v.z * kv.z + v.w * kv.w;
            }
        }
#pragma unroll
        for (int off = 16; off; off >>= 1) {
            nrm += __shfl_xor_sync(0xFFFFFFFFu, nrm, off);
#pragma unroll
            for (int r = 0; r < 16; r++)
                dot[r] += __shfl_xor_sync(0xFFFFFFFFu, dot[r], off);
        }
        float inv = 1.0f / fmaxf(sqrtf(nrm), 1e-8f);
        float w[16];
#pragma unroll
        for (int r = 0; r < 16; r++) w[r] = pas[r] * dot[r] * inv;

        float4* yo = (float4*)(y + ((size_t)b * PP + p) * DD);
#pragma unroll
        for (int c = 0; c < 8; c++) {
            float4 acc = {0.f, 0.f, 0.f, 0.f};
#pragma unroll
            for (int r = 0; r < 16; r++) {
                float4 vv = ((const float4*)(Vs + r * DD))[c * 32 + lane];
                acc.x += w[r] * vv.x;
                acc.y += w[r] * vv.y;
                acc.z += w[r] * vv.z;
                acc.w += w[r] * vv.w;
            }
            yo[c * 32 + lane] = acc;
        }
    }
}

// ---------------- launch ----------------
extern "C" void kernel_launch(void* const* d_in, const int* in_sizes, int n_in,
                              void* d_out, int out_size) {
    const float* x = (const float*)d_in[0];
    const float* h = (const float*)d_in[1];
    const float* sur = (const float*)d_in[2];
    const unsigned int* mask = (const unsigned int*)d_in[3];
    const float* pmK = (const float*)d_in[4];
    const float* pmV = (const float*)d_in[5];
    const float* pa = (const float*)d_in[6];
    const float* eK0 = (const float*)d_in[7];
    const float* eV0 = (const float*)d_in[8];
    const float* Wk = (const float*)d_in[9];
    const float* bk = (const float*)d_in[10];
    const float* Wv = (const float*)d_in[11];
    const float* bv = (const float*)d_in[12];

    float* out = (float*)d_out;
    float* y = out;
    float* outK = out + (size_t)BS * PP * DD;
    float* outV = outK + (size_t)BS * RR * DD;

    static const int READOUT_SMEM = RR * DD * 2 * (int)sizeof(float);
    cudaFuncSetAttribute(readout_kernel,
                         cudaFuncAttributeMaxDynamicSharedMemorySize, READOUT_SMEM);
    cudaFuncSetAttribute(mma_gemm_kernel,
                         cudaFuncAttributeMaxDynamicSharedMemorySize, GSMEM);

    coeff_kernel<<<BS, PP>>>(sur, mask);
    convA_kernel<<<MM * DD / 4 / 256, 256>>>(x);
    convB_kernel<<<DD * DD / 4 / 256, 256>>>(Wk);
    hbar_kernel<<<dim3(BS, DD / 256, 4), 256>>>(h);
    mma_gemm_kernel<<<dim3(DD / 128, MM / 128), 256, GSMEM>>>(bk);
    coefk_kernel<<<MM / 256, 256>>>();
    eligk_kernel<<<dim3(BS, DD / 256, 4), 256>>>();
    vgemm_kernel<<<dim3(BS / 4, DD / 256), 256>>>(Wv, bv);
    expand_kernel<<<(BS * RR * DD + 255) / 256, 256>>>(eK0, eV0, outK, outV);
    readout_kernel<<<dim3(BS, PP / 32), 256, READOUT_SMEM>>>(x, pmK, pmV, pa, y);
}

// round 8
// speedup vs baseline: 1.5982x; 1.1809x over previous
#include <cuda_runtime.h>
#include <cuda_fp16.h>
#include <cstdint>

#define BS 32
#define PP 128
#define RR 16
#define DD 1024
#define RHO 0.97f
#define MM (BS * PP)   // 4096 rows of the big GEMM

// ---------------- scratch (no allocations allowed) ----------------
__device__ __half g_Ch[(size_t)MM * DD];             // k_cand fp16 (8 MB)
__device__ __half g_Ah[(size_t)MM * DD];             // x fp16 (8 MB)
__device__ __half g_Bh[(size_t)DD * DD];             // Wk fp16 [K][N] (2 MB)
__device__ float g_normp[MM * 32];                   // per-row sumsq partials
__device__ float g_w[MM];
__device__ float g_coefK[MM];
__device__ float g_Atot[BS];
__device__ float g_wsum[BS];
__device__ float g_hbarp[8 * BS * DD];               // p-split partials
__device__ float g_eligKp[8 * BS * DD];              // p-split partials
__device__ float g_eligV[BS * DD];

// ---------------- PTX helpers ----------------
__device__ __forceinline__ uint32_t smem_u32(const void* p) {
    return (uint32_t)__cvta_generic_to_shared(p);
}
__device__ __forceinline__ void cp_async16(uint32_t dst, const void* src) {
    asm volatile("cp.async.cg.shared.global [%0], [%1], 16;" :: "r"(dst), "l"(src));
}
#define CP_COMMIT() asm volatile("cp.async.commit_group;" ::: "memory")
#define CP_WAIT2()  asm volatile("cp.async.wait_group 2;" ::: "memory")
#define CP_WAIT0()  asm volatile("cp.async.wait_group 0;" ::: "memory")

__device__ __forceinline__ void ldm_x4(uint32_t* r, uint32_t addr) {
    asm volatile("ldmatrix.sync.aligned.m8n8.x4.shared.b16 {%0,%1,%2,%3}, [%4];"
                 : "=r"(r[0]), "=r"(r[1]), "=r"(r[2]), "=r"(r[3]) : "r"(addr));
}
__device__ __forceinline__ void ldm_x4_t(uint32_t& r0, uint32_t& r1, uint32_t& r2,
                                         uint32_t& r3, uint32_t addr) {
    asm volatile("ldmatrix.sync.aligned.m8n8.x4.trans.shared.b16 {%0,%1,%2,%3}, [%4];"
                 : "=r"(r0), "=r"(r1), "=r"(r2), "=r"(r3) : "r"(addr));
}
__device__ __forceinline__ void mma_f16(float* c, const uint32_t* a, const uint32_t* b) {
    asm volatile("mma.sync.aligned.m16n8k16.row.col.f32.f16.f16.f32 "
                 "{%0,%1,%2,%3}, {%4,%5,%6,%7}, {%8,%9}, {%0,%1,%2,%3};"
                 : "+f"(c[0]), "+f"(c[1]), "+f"(c[2]), "+f"(c[3])
                 : "r"(a[0]), "r"(a[1]), "r"(a[2]), "r"(a[3]), "r"(b[0]), "r"(b[1]));
}

// ---------------- 1) per-batch coefficients ----------------
__global__ void coeff_kernel(const float* __restrict__ surprise,
                             const unsigned int* __restrict__ mask) {
    int b = blockIdx.x, p = threadIdx.x;  // 128 threads
    __shared__ float a_s[PP], c_s[PP], w_s[PP];
    float g = fminf(fmaxf(surprise[b * PP + p] * 0.2f, 0.0f), 1.0f);
    float a = (mask[b * PP + p] != 0u) ? 0.0f : RHO;
    a_s[p] = a;
    __syncthreads();
    if (p == 0) {
        float c = 1.0f;
        for (int q = PP - 1; q >= 0; --q) { c_s[q] = c; c *= a_s[q]; }
        g_Atot[b] = c;
    }
    __syncthreads();
    float w = g * c_s[p];
    w_s[p] = w;
    g_w[b * PP + p] = w;
    __syncthreads();
    if (p == 0) {
        float s = 0.0f;
        for (int q = 0; q < PP; q++) s += w_s[q];
        g_wsum[b] = s;
    }
}

// ---------------- 2) fp32 -> fp16 conversions (8 elems/thread) ----------------
__global__ __launch_bounds__(256) void convA_kernel(const float* __restrict__ x) {
    size_t i8 = (size_t)blockIdx.x * 256 + threadIdx.x;  // over MM*DD/8
    const float4* xf = (const float4*)x;
    float4 a = xf[i8 * 2], b = xf[i8 * 2 + 1];
    __half2 h0 = __floats2half2_rn(a.x, a.y);
    __half2 h1 = __floats2half2_rn(a.z, a.w);
    __half2 h2 = __floats2half2_rn(b.x, b.y);
    __half2 h3 = __floats2half2_rn(b.z, b.w);
    *(uint4*)&g_Ah[i8 * 8] = make_uint4(*(uint32_t*)&h0, *(uint32_t*)&h1,
                                        *(uint32_t*)&h2, *(uint32_t*)&h3);
}
__global__ __launch_bounds__(256) void convB_kernel(const float* __restrict__ Wk) {
    size_t i8 = (size_t)blockIdx.x * 256 + threadIdx.x;  // over DD*DD/8
    const float4* xf = (const float4*)Wk;
    float4 a = xf[i8 * 2], b = xf[i8 * 2 + 1];
    __half2 h0 = __floats2half2_rn(a.x, a.y);
    __half2 h1 = __floats2half2_rn(a.z, a.w);
    __half2 h2 = __floats2half2_rn(b.x, b.y);
    __half2 h3 = __floats2half2_rn(b.z, b.w);
    *(uint4*)&g_Bh[i8 * 8] = make_uint4(*(uint32_t*)&h0, *(uint32_t*)&h1,
                                        *(uint32_t*)&h2, *(uint32_t*)&h3);
}

// ---------------- 3) hbar partials: grid (BS, 1, 8), float4 loads ----------------
__global__ __launch_bounds__(256) void hbar_kernel(const float* __restrict__ h) {
    int b = blockIdx.x, s = blockIdx.z;
    int t = threadIdx.x;  // float4 column index, 256 covers the row
    __shared__ float cs[16];
    if (t < 16) cs[t] = g_w[b * PP + s * 16 + t];
    __syncthreads();
    const float4* sp = (const float4*)(h + ((size_t)b * PP + s * 16) * DD) + t;
    float4 acc = {0.f, 0.f, 0.f, 0.f};
#pragma unroll
    for (int p = 0; p < 16; p++) {
        float4 v = sp[(size_t)p * 256];
        float c = cs[p];
        acc.x += c * v.x; acc.y += c * v.y; acc.z += c * v.z; acc.w += c * v.w;
    }
    ((float4*)&g_hbarp[((s * BS + b) << 10)])[t] = acc;
}

// ---------------- 4) single-fp16 mma.sync GEMM, 4-stage cp.async ----------------
// C = fp16(X) @ fp16(Wk) + bk, K=1024 (32 tiles of 32).
// Block 128x128, 8 warps (2x4), warp tile 64x32 = 4x4 m16n8k16.
#define ASTB 80       // A smem row stride bytes (64 + 16 pad)
#define BSTB 272      // B smem row stride bytes (256 + 16 pad)
#define ASTG_A 10240
#define STAGE_B 18944
#define NSTAGE 4
#define GSMEM (NSTAGE * STAGE_B)   // 75776 B

__global__ __launch_bounds__(256) void mma_gemm_kernel(const float* __restrict__ bias) {
    extern __shared__ char smem[];
    uint32_t sb = smem_u32(smem);
    int tid = threadIdx.x;
    int lane = tid & 31, warp = tid >> 5;
    int wm = warp >> 2, wn = warp & 3;
    int bm = blockIdx.y * 128, bn = blockIdx.x * 128;

    float acc[4][4][4];
#pragma unroll
    for (int i = 0; i < 4; i++)
#pragma unroll
        for (int j = 0; j < 4; j++)
#pragma unroll
            for (int k = 0; k < 4; k++) acc[i][j][k] = 0.0f;

    int aid0 = tid * 2;
    int arow0 = aid0 >> 2, ach0 = aid0 & 3;
    int arow1 = (aid0 + 1) >> 2, ach1 = (aid0 + 1) & 3;
    int brow0 = aid0 >> 4, bch0 = aid0 & 15;
    int brow1 = (aid0 + 1) >> 4, bch1 = (aid0 + 1) & 15;

    auto issue_stage = [&](int kt, int slot) {
        int ak = kt * 32;
        uint32_t sA = sb + slot * STAGE_B;
        uint32_t sB = sA + ASTG_A;
        cp_async16(sA + arow0 * ASTB + ach0 * 16,
                   &g_Ah[(size_t)(bm + arow0) * 1024 + ak + ach0 * 8]);
        cp_async16(sA + arow1 * ASTB + ach1 * 16,
                   &g_Ah[(size_t)(bm + arow1) * 1024 + ak + ach1 * 8]);
        cp_async16(sB + brow0 * BSTB + bch0 * 16,
                   &g_Bh[(size_t)(ak + brow0) * 1024 + bn + bch0 * 8]);
        cp_async16(sB + brow1 * BSTB + bch1 * 16,
                   &g_Bh[(size_t)(ak + brow1) * 1024 + bn + bch1 * 8]);
    };

    int g8 = lane >> 3;
    int r8 = lane & 7;
    int aRowOff = wm * 64 + r8 + (g8 & 1) * 8;
    int aColB = (g8 >> 1) * 16;
    int bRowOff = r8 + (g8 & 1) * 8;
    int bColB = (wn * 32 + (g8 >> 1) * 8) * 2;

#pragma unroll
    for (int i = 0; i < NSTAGE - 1; i++) {
        issue_stage(i, i);
        CP_COMMIT();
    }

    for (int i = 0; i < 32; i++) {
        CP_WAIT2();
        __syncthreads();
        int slot = i & (NSTAGE - 1);
        uint32_t sA = sb + slot * STAGE_B;
        uint32_t sB = sA + ASTG_A;
#pragma unroll
        for (int ks = 0; ks < 32; ks += 16) {
            uint32_t afr[4][4], bfr[4][2];
#pragma unroll
            for (int tm = 0; tm < 4; tm++)
                ldm_x4(afr[tm], sA + (aRowOff + tm * 16) * ASTB + aColB + ks * 2);
#pragma unroll
            for (int tp = 0; tp < 2; tp++) {
                uint32_t r0, r1, r2, r3;
                ldm_x4_t(r0, r1, r2, r3,
                         sB + (bRowOff + ks) * BSTB + bColB + tp * 32);
                bfr[tp * 2][0] = r0; bfr[tp * 2][1] = r1;
                bfr[tp * 2 + 1][0] = r2; bfr[tp * 2 + 1][1] = r3;
            }
#pragma unroll
            for (int tm = 0; tm < 4; tm++)
#pragma unroll
                for (int tn = 0; tn < 4; tn++)
                    mma_f16(acc[tm][tn], afr[tm], bfr[tn]);
        }
        if (i + NSTAGE - 1 < 32) issue_stage(i + NSTAGE - 1, (i + NSTAGE - 1) & (NSTAGE - 1));
        CP_COMMIT();
    }
    CP_WAIT0();

    // ---- epilogue: bias add, fp16 store, deterministic sumsq partials ----
    int gq = lane >> 2;
    int cq = lane & 3;
#pragma unroll
    for (int tm = 0; tm < 4; tm++) {
        int row0 = bm + wm * 64 + tm * 16 + gq;
        float s0 = 0.0f, s1 = 0.0f;
#pragma unroll
        for (int tn = 0; tn < 4; tn++) {
            int col = bn + wn * 32 + tn * 8 + cq * 2;
            float2 bb = *(const float2*)&bias[col];
            float v0 = acc[tm][tn][0] + bb.x;
            float v1 = acc[tm][tn][1] + bb.y;
            float v2 = acc[tm][tn][2] + bb.x;
            float v3 = acc[tm][tn][3] + bb.y;
            *(__half2*)&g_Ch[(size_t)row0 * DD + col] = __floats2half2_rn(v0, v1);
            *(__half2*)&g_Ch[(size_t)(row0 + 8) * DD + col] = __floats2half2_rn(v2, v3);
            s0 += v0 * v0 + v1 * v1;
            s1 += v2 * v2 + v3 * v3;
        }
        s0 += __shfl_xor_sync(0xFFFFFFFFu, s0, 1);
        s0 += __shfl_xor_sync(0xFFFFFFFFu, s0, 2);
        s1 += __shfl_xor_sync(0xFFFFFFFFu, s1, 1);
        s1 += __shfl_xor_sync(0xFFFFFFFFu, s1, 2);
        if (cq == 0) {
            int slot = blockIdx.x * 4 + wn;
            g_normp[(size_t)row0 * 32 + slot] = s0;
            g_normp[(size_t)(row0 + 8) * 32 + slot] = s1;
        }
    }
}

// ---------------- 5) coefK = w / max(norm, eps) ----------------
__global__ __launch_bounds__(256) void coefk_kernel() {
    int row = blockIdx.x * 256 + threadIdx.x;  // 4096
    const float* p = &g_normp[row * 32];
    float s = 0.0f;
#pragma unroll
    for (int i = 0; i < 32; i++) s += p[i];
    g_coefK[row] = g_w[row] / fmaxf(sqrtf(s), 1e-8f);
}

// ---------------- 6) eligK partials: grid (BS, 2, 8), half2 ----------------
__global__ __launch_bounds__(256) void eligk_kernel() {
    int b = blockIdx.x, s = blockIdx.z;
    int d2 = blockIdx.y * 256 + threadIdx.x;  // half2 index 0..511
    __shared__ float cs[16];
    if (threadIdx.x < 16) cs[threadIdx.x] = g_coefK[b * PP + s * 16 + threadIdx.x];
    __syncthreads();
    const __half2* sp = (const __half2*)g_Ch + ((size_t)b * PP + s * 16) * (DD / 2) + d2;
    float2 acc = {0.f, 0.f};
#pragma unroll
    for (int p = 0; p < 16; p++) {
        float2 v = __half22float2(sp[(size_t)p * (DD / 2)]);
        float c = cs[p];
        acc.x += c * v.x;
        acc.y += c * v.y;
    }
    int base = ((s * BS + b) << 10) + d2 * 2;
    g_eligKp[base] = acc.x;
    g_eligKp[base + 1] = acc.y;
}

// ---------------- 7) eligV[b,:] = hbar[b] @ Wv + wsum[b]*bv ----------------
__global__ __launch_bounds__(256) void vgemm_kernel(const float* __restrict__ Wv,
                                                    const float* __restrict__ bv) {
    int bg = blockIdx.x;
    int e = blockIdx.y * 256 + threadIdx.x;
    __shared__ float hs[4][DD];
    for (int i = threadIdx.x; i < 4 * DD; i += 256) {
        int bl = i >> 10, d = i & 1023;
        int b = bg * 4 + bl;
        float v = 0.0f;
#pragma unroll
        for (int s = 0; s < 8; s++) v += g_hbarp[((s * BS + b) << 10) + d];
        hs[bl][d] = v;
    }
    __syncthreads();
    float acc0 = 0.f, acc1 = 0.f, acc2 = 0.f, acc3 = 0.f;
#pragma unroll 8
    for (int d = 0; d < DD; d++) {
        float wv = Wv[(size_t)d * DD + e];
        acc0 += hs[0][d] * wv;
        acc1 += hs[1][d] * wv;
        acc2 += hs[2][d] * wv;
        acc3 += hs[3][d] * wv;
    }
    float bve = bv[e];
    g_eligV[(bg * 4 + 0) * DD + e] = acc0 + g_wsum[bg * 4 + 0] * bve;
    g_eligV[(bg * 4 + 1) * DD + e] = acc1 + g_wsum[bg * 4 + 1] * bve;
    g_eligV[(bg * 4 + 2) * DD + e] = acc2 + g_wsum[bg * 4 + 2] * bve;
    g_eligV[(bg * 4 + 3) * DD + e] = acc3 + g_wsum[bg * 4 + 3] * bve;
}

// ---------------- 8) expand to [BS,R,D] outputs ----------------
__global__ __launch_bounds__(256) void expand_kernel(const float* __restrict__ eK0,
                                                     const float* __restrict__ eV0,
                                                     float* __restrict__ outK,
                                                     float* __restrict__ outV) {
    int idx = blockIdx.x * 256 + threadIdx.x;
    if (idx >= BS * RR * DD) return;
    int b = idx / (RR * DD);
    int d = idx & (DD - 1);
    float A = g_Atot[b];
    float ek = 0.0f;
#pragma unroll
    for (int s = 0; s < 8; s++) ek += g_eligKp[((s * BS + b) << 10) + d];
    outK[idx] = A * eK0[idx] + ek;
    outV[idx] = A * eV0[idx] + g_eligV[b * DD + d];
}

// ---------------- 9) readout: y_pm ----------------
__global__ __launch_bounds__(256) void readout_kernel(const float* __restrict__ x,
                                                      const float* __restrict__ pmK,
                                                      const float* __restrict__ pmV,
                                                      const float* __restrict__ pa,
                                                      float* __restrict__ y) {
    extern __shared__ float sm[];
    float* Ks = sm;
    float* Vs = sm + RR * DD;
    __shared__ float pas[RR];
    int b = blockIdx.x;
    int tid = threadIdx.x;

    const float4* Kg = (const float4*)(pmK + (size_t)b * RR * DD);
    const float4* Vg = (const float4*)(pmV + (size_t)b * RR * DD);
    float4* K4 = (float4*)Ks;
    float4* V4 = (float4*)Vs;
    for (int i = tid; i < RR * DD / 4; i += 256) {
        K4[i] = Kg[i];
        V4[i] = Vg[i];
    }
    if (tid < RR) pas[tid] = pa[b * RR + tid];
    __syncthreads();

    int warp = tid >> 5, lane = tid & 31;
    for (int t0 = 0; t0 < 32; t0 += 8) {
        int p = blockIdx.y * 32 + t0 + warp;
        const float4* xr = (const float4*)(x + ((size_t)b * PP + p) * DD);
        float nrm = 0.0f;
        float dot[16];
#pragma unroll
        for (int r = 0; r < 16; r++) dot[r] = 0.0f;
#pragma unroll
        for (int c = 0; c < 8; c++) {
            float4 v = xr[c * 32 + lane];
            nrm += v.x * v.x + v.y * v.y + v.z * v.z + v.w * v.w;
#pragma unroll
            for (int r = 0; r < 16; r++) {
                float4 kv = ((const float4*)(Ks + r * DD))[c * 32 + lane];
                dot[r] += v.x * kv.x + v.y * kv.y + v.z * kv.z + v.w * kv.w;
            }
        }
#pragma unroll
        for (int off = 16; off; off >>= 1) {
            nrm += __shfl_xor_sync(0xFFFFFFFFu, nrm, off);
#pragma unroll
            for (int r = 0; r < 16; r++)
                dot[r] += __shfl_xor_sync(0xFFFFFFFFu, dot[r], off);
        }
        float inv = 1.0f / fmaxf(sqrtf(nrm), 1e-8f);
        float w[16];
#pragma unroll
        for (int r = 0; r < 16; r++) w[r] = pas[r] * dot[r] * inv;

        float4* yo = (float4*)(y + ((size_t)b * PP + p) * DD);
#pragma unroll
        for (int c = 0; c < 8; c++) {
            float4 acc = {0.f, 0.f, 0.f, 0.f};
#pragma unroll
            for (int r = 0; r < 16; r++) {
                float4 vv = ((const float4*)(Vs + r * DD))[c * 32 + lane];
                acc.x += w[r] * vv.x;
                acc.y += w[r] * vv.y;
                acc.z += w[r] * vv.z;
                acc.w += w[r] * vv.w;
            }
            yo[c * 32 + lane] = acc;
        }
    }
}

// ---------------- launch ----------------
extern "C" void kernel_launch(void* const* d_in, const int* in_sizes, int n_in,
                              void* d_out, int out_size) {
    const float* x = (const float*)d_in[0];
    const float* h = (const float*)d_in[1];
    const float* sur = (const float*)d_in[2];
    const unsigned int* mask = (const unsigned int*)d_in[3];
    const float* pmK = (const float*)d_in[4];
    const float* pmV = (const float*)d_in[5];
    const float* pa = (const float*)d_in[6];
    const float* eK0 = (const float*)d_in[7];
    const float* eV0 = (const float*)d_in[8];
    const float* Wk = (const float*)d_in[9];
    const float* bk = (const float*)d_in[10];
    const float* Wv = (const float*)d_in[11];
    const float* bv = (const float*)d_in[12];

    float* out = (float*)d_out;
    float* y = out;
    float* outK = out + (size_t)BS * PP * DD;
    float* outV = outK + (size_t)BS * RR * DD;

    static const int READOUT_SMEM = RR * DD * 2 * (int)sizeof(float);
    cudaFuncSetAttribute(readout_kernel,
                         cudaFuncAttributeMaxDynamicSharedMemorySize, READOUT_SMEM);
    cudaFuncSetAttribute(mma_gemm_kernel,
                         cudaFuncAttributeMaxDynamicSharedMemorySize, GSMEM);

    coeff_kernel<<<BS, PP>>>(sur, mask);
    convA_kernel<<<MM * DD / 8 / 256, 256>>>(x);
    convB_kernel<<<DD * DD / 8 / 256, 256>>>(Wk);
    hbar_kernel<<<dim3(BS, 1, 8), 256>>>(h);
    mma_gemm_kernel<<<dim3(DD / 128, MM / 128), 256, GSMEM>>>(bk);
    coefk_kernel<<<MM / 256, 256>>>();
    eligk_kernel<<<dim3(BS, 2, 8), 256>>>();
    vgemm_kernel<<<dim3(BS / 4, DD / 256), 256>>>(Wv, bv);
    expand_kernel<<<(BS * RR * DD + 255) / 256, 256>>>(eK0, eV0, outK, outV);
    readout_kernel<<<dim3(BS, PP / 32), 256, READOUT_SMEM>>>(x, pmK, pmV, pa, y);
}

// round 9
// speedup vs baseline: 4.1250x; 2.5811x over previous
#include <cuda_runtime.h>
#include <cuda_fp16.h>
#include <cstdint>

#define BS 32
#define PP 128
#define RR 16
#define DD 1024
#define RHO 0.97f
#define MM (BS * PP)   // 4096 rows of the big GEMM

// ---------------- scratch (no allocations allowed) ----------------
__device__ __half g_Ch[(size_t)MM * DD];             // k_cand fp16 (8 MB)
__device__ __half g_Ah[(size_t)MM * DD];             // x fp16 (8 MB)
__device__ __half g_Bh[(size_t)DD * DD];             // Wk fp16 [K][N] (2 MB)
__device__ float g_normp[MM * 32];                   // per-row sumsq partials
__device__ float g_w[MM];
__device__ float g_Atot[BS];
__device__ float g_wsum[BS];
__device__ float g_hbarp[8 * BS * DD];               // p-split partials
__device__ float g_eligKp[8 * BS * DD];              // p-split partials
__device__ float g_eligVp[16 * BS * DD];             // k-split partials (2 MB)

// ---------------- PTX helpers ----------------
__device__ __forceinline__ uint32_t smem_u32(const void* p) {
    return (uint32_t)__cvta_generic_to_shared(p);
}
__device__ __forceinline__ void cp_async16(uint32_t dst, const void* src) {
    asm volatile("cp.async.cg.shared.global [%0], [%1], 16;" :: "r"(dst), "l"(src));
}
#define CP_COMMIT() asm volatile("cp.async.commit_group;" ::: "memory")
#define CP_WAIT2()  asm volatile("cp.async.wait_group 2;" ::: "memory")
#define CP_WAIT0()  asm volatile("cp.async.wait_group 0;" ::: "memory")

__device__ __forceinline__ void ldm_x4(uint32_t* r, uint32_t addr) {
    asm volatile("ldmatrix.sync.aligned.m8n8.x4.shared.b16 {%0,%1,%2,%3}, [%4];"
                 : "=r"(r[0]), "=r"(r[1]), "=r"(r[2]), "=r"(r[3]) : "r"(addr));
}
__device__ __forceinline__ void ldm_x4_t(uint32_t& r0, uint32_t& r1, uint32_t& r2,
                                         uint32_t& r3, uint32_t addr) {
    asm volatile("ldmatrix.sync.aligned.m8n8.x4.trans.shared.b16 {%0,%1,%2,%3}, [%4];"
                 : "=r"(r0), "=r"(r1), "=r"(r2), "=r"(r3) : "r"(addr));
}
__device__ __forceinline__ void mma_f16(float* c, const uint32_t* a, const uint32_t* b) {
    asm volatile("mma.sync.aligned.m16n8k16.row.col.f32.f16.f16.f32 "
                 "{%0,%1,%2,%3}, {%4,%5,%6,%7}, {%8,%9}, {%0,%1,%2,%3};"
                 : "+f"(c[0]), "+f"(c[1]), "+f"(c[2]), "+f"(c[3])
                 : "r"(a[0]), "r"(a[1]), "r"(a[2]), "r"(a[3]), "r"(b[0]), "r"(b[1]));
}

// ---------------- 1) per-batch coefficients ----------------
__global__ void coeff_kernel(const float* __restrict__ surprise,
                             const unsigned int* __restrict__ mask) {
    int b = blockIdx.x, p = threadIdx.x;  // 128 threads
    __shared__ float a_s[PP], c_s[PP], w_s[PP];
    float g = fminf(fmaxf(surprise[b * PP + p] * 0.2f, 0.0f), 1.0f);
    float a = (mask[b * PP + p] != 0u) ? 0.0f : RHO;
    a_s[p] = a;
    __syncthreads();
    if (p == 0) {
        float c = 1.0f;
        for (int q = PP - 1; q >= 0; --q) { c_s[q] = c; c *= a_s[q]; }
        g_Atot[b] = c;
    }
    __syncthreads();
    float w = g * c_s[p];
    w_s[p] = w;
    g_w[b * PP + p] = w;
    __syncthreads();
    if (p == 0) {
        float s = 0.0f;
        for (int q = 0; q < PP; q++) s += w_s[q];
        g_wsum[b] = s;
    }
}

// ---------------- 2) fp32 -> fp16 conversions (8 elems/thread) ----------------
__global__ __launch_bounds__(256) void convA_kernel(const float* __restrict__ x) {
    size_t i8 = (size_t)blockIdx.x * 256 + threadIdx.x;  // over MM*DD/8
    const float4* xf = (const float4*)x;
    float4 a = xf[i8 * 2], b = xf[i8 * 2 + 1];
    __half2 h0 = __floats2half2_rn(a.x, a.y);
    __half2 h1 = __floats2half2_rn(a.z, a.w);
    __half2 h2 = __floats2half2_rn(b.x, b.y);
    __half2 h3 = __floats2half2_rn(b.z, b.w);
    *(uint4*)&g_Ah[i8 * 8] = make_uint4(*(uint32_t*)&h0, *(uint32_t*)&h1,
                                        *(uint32_t*)&h2, *(uint32_t*)&h3);
}
__global__ __launch_bounds__(256) void convB_kernel(const float* __restrict__ Wk) {
    size_t i8 = (size_t)blockIdx.x * 256 + threadIdx.x;  // over DD*DD/8
    const float4* xf = (const float4*)Wk;
    float4 a = xf[i8 * 2], b = xf[i8 * 2 + 1];
    __half2 h0 = __floats2half2_rn(a.x, a.y);
    __half2 h1 = __floats2half2_rn(a.z, a.w);
    __half2 h2 = __floats2half2_rn(b.x, b.y);
    __half2 h3 = __floats2half2_rn(b.z, b.w);
    *(uint4*)&g_Bh[i8 * 8] = make_uint4(*(uint32_t*)&h0, *(uint32_t*)&h1,
                                        *(uint32_t*)&h2, *(uint32_t*)&h3);
}

// ---------------- 3) readout: y_pm (depends only on raw inputs) ----------------
__global__ __launch_bounds__(256) void readout_kernel(const float* __restrict__ x,
                                                      const float* __restrict__ pmK,
                                                      const float* __restrict__ pmV,
                                                      const float* __restrict__ pa,
                                                      float* __restrict__ y) {
    extern __shared__ float sm[];
    float* Ks = sm;
    float* Vs = sm + RR * DD;
    __shared__ float pas[RR];
    int b = blockIdx.x;
    int tid = threadIdx.x;

    const float4* Kg = (const float4*)(pmK + (size_t)b * RR * DD);
    const float4* Vg = (const float4*)(pmV + (size_t)b * RR * DD);
    float4* K4 = (float4*)Ks;
    float4* V4 = (float4*)Vs;
    for (int i = tid; i < RR * DD / 4; i += 256) {
        K4[i] = Kg[i];
        V4[i] = Vg[i];
    }
    if (tid < RR) pas[tid] = pa[b * RR + tid];
    __syncthreads();

    int warp = tid >> 5, lane = tid & 31;
    for (int t0 = 0; t0 < 32; t0 += 8) {
        int p = blockIdx.y * 32 + t0 + warp;
        const float4* xr = (const float4*)(x + ((size_t)b * PP + p) * DD);
        float nrm = 0.0f;
        float dot[16];
#pragma unroll
        for (int r = 0; r < 16; r++) dot[r] = 0.0f;
#pragma unroll
        for (int c = 0; c < 8; c++) {
            float4 v = xr[c * 32 + lane];
            nrm += v.x * v.x + v.y * v.y + v.z * v.z + v.w * v.w;
#pragma unroll
            for (int r = 0; r < 16; r++) {
                float4 kv = ((const float4*)(Ks + r * DD))[c * 32 + lane];
                dot[r] += v.x * kv.x + v.y * kv.y + v.z * kv.z + v.w * kv.w;
            }
        }
#pragma unroll
        for (int off = 16; off; off >>= 1) {
            nrm += __shfl_xor_sync(0xFFFFFFFFu, nrm, off);
#pragma unroll
            for (int r = 0; r < 16; r++)
                dot[r] += __shfl_xor_sync(0xFFFFFFFFu, dot[r], off);
        }
        float inv = 1.0f / fmaxf(sqrtf(nrm), 1e-8f);
        float w[16];
#pragma unroll
        for (int r = 0; r < 16; r++) w[r] = pas[r] * dot[r] * inv;

        float4* yo = (float4*)(y + ((size_t)b * PP + p) * DD);
#pragma unroll
        for (int c = 0; c < 8; c++) {
            float4 acc = {0.f, 0.f, 0.f, 0.f};
#pragma unroll
            for (int r = 0; r < 16; r++) {
                float4 vv = ((const float4*)(Vs + r * DD))[c * 32 + lane];
                acc.x += w[r] * vv.x;
                acc.y += w[r] * vv.y;
                acc.z += w[r] * vv.z;
                acc.w += w[r] * vv.w;
            }
            yo[c * 32 + lane] = acc;
        }
    }
}

// ---------------- 4) single-fp16 mma.sync GEMM, 4-stage cp.async ----------------
#define ASTB 80       // A smem row stride bytes (64 + 16 pad)
#define BSTB 272      // B smem row stride bytes (256 + 16 pad)
#define ASTG_A 10240
#define STAGE_B 18944
#define NSTAGE 4
#define GSMEM (NSTAGE * STAGE_B)   // 75776 B

__global__ __launch_bounds__(256) void mma_gemm_kernel(const float* __restrict__ bias) {
    extern __shared__ char smem[];
    uint32_t sb = smem_u32(smem);
    int tid = threadIdx.x;
    int lane = tid & 31, warp = tid >> 5;
    int wm = warp >> 2, wn = warp & 3;
    int bm = blockIdx.y * 128, bn = blockIdx.x * 128;

    float acc[4][4][4];
#pragma unroll
    for (int i = 0; i < 4; i++)
#pragma unroll
        for (int j = 0; j < 4; j++)
#pragma unroll
            for (int k = 0; k < 4; k++) acc[i][j][k] = 0.0f;

    int aid0 = tid * 2;
    int arow0 = aid0 >> 2, ach0 = aid0 & 3;
    int arow1 = (aid0 + 1) >> 2, ach1 = (aid0 + 1) & 3;
    int brow0 = aid0 >> 4, bch0 = aid0 & 15;
    int brow1 = (aid0 + 1) >> 4, bch1 = (aid0 + 1) & 15;

    auto issue_stage = [&](int kt, int slot) {
        int ak = kt * 32;
        uint32_t sA = sb + slot * STAGE_B;
        uint32_t sB = sA + ASTG_A;
        cp_async16(sA + arow0 * ASTB + ach0 * 16,
                   &g_Ah[(size_t)(bm + arow0) * 1024 + ak + ach0 * 8]);
        cp_async16(sA + arow1 * ASTB + ach1 * 16,
                   &g_Ah[(size_t)(bm + arow1) * 1024 + ak + ach1 * 8]);
        cp_async16(sB + brow0 * BSTB + bch0 * 16,
                   &g_Bh[(size_t)(ak + brow0) * 1024 + bn + bch0 * 8]);
        cp_async16(sB + brow1 * BSTB + bch1 * 16,
                   &g_Bh[(size_t)(ak + brow1) * 1024 + bn + bch1 * 8]);
    };

    int g8 = lane >> 3;
    int r8 = lane & 7;
    int aRowOff = wm * 64 + r8 + (g8 & 1) * 8;
    int aColB = (g8 >> 1) * 16;
    int bRowOff = r8 + (g8 & 1) * 8;
    int bColB = (wn * 32 + (g8 >> 1) * 8) * 2;

#pragma unroll
    for (int i = 0; i < NSTAGE - 1; i++) {
        issue_stage(i, i);
        CP_COMMIT();
    }

    for (int i = 0; i < 32; i++) {
        CP_WAIT2();
        __syncthreads();
        int slot = i & (NSTAGE - 1);
        uint32_t sA = sb + slot * STAGE_B;
        uint32_t sB = sA + ASTG_A;
#pragma unroll
        for (int ks = 0; ks < 32; ks += 16) {
            uint32_t afr[4][4], bfr[4][2];
#pragma unroll
            for (int tm = 0; tm < 4; tm++)
                ldm_x4(afr[tm], sA + (aRowOff + tm * 16) * ASTB + aColB + ks * 2);
#pragma unroll
            for (int tp = 0; tp < 2; tp++) {
                uint32_t r0, r1, r2, r3;
                ldm_x4_t(r0, r1, r2, r3,
                         sB + (bRowOff + ks) * BSTB + bColB + tp * 32);
                bfr[tp * 2][0] = r0; bfr[tp * 2][1] = r1;
                bfr[tp * 2 + 1][0] = r2; bfr[tp * 2 + 1][1] = r3;
            }
#pragma unroll
            for (int tm = 0; tm < 4; tm++)
#pragma unroll
                for (int tn = 0; tn < 4; tn++)
                    mma_f16(acc[tm][tn], afr[tm], bfr[tn]);
        }
        if (i + NSTAGE - 1 < 32) issue_stage(i + NSTAGE - 1, (i + NSTAGE - 1) & (NSTAGE - 1));
        CP_COMMIT();
    }
    CP_WAIT0();

    // ---- epilogue: bias add, fp16 store, deterministic sumsq partials ----
    int gq = lane >> 2;
    int cq = lane & 3;
#pragma unroll
    for (int tm = 0; tm < 4; tm++) {
        int row0 = bm + wm * 64 + tm * 16 + gq;
        float s0 = 0.0f, s1 = 0.0f;
#pragma unroll
        for (int tn = 0; tn < 4; tn++) {
            int col = bn + wn * 32 + tn * 8 + cq * 2;
            float2 bb = *(const float2*)&bias[col];
            float v0 = acc[tm][tn][0] + bb.x;
            float v1 = acc[tm][tn][1] + bb.y;
            float v2 = acc[tm][tn][2] + bb.x;
            float v3 = acc[tm][tn][3] + bb.y;
            *(__half2*)&g_Ch[(size_t)row0 * DD + col] = __floats2half2_rn(v0, v1);
            *(__half2*)&g_Ch[(size_t)(row0 + 8) * DD + col] = __floats2half2_rn(v2, v3);
            s0 += v0 * v0 + v1 * v1;
            s1 += v2 * v2 + v3 * v3;
        }
        s0 += __shfl_xor_sync(0xFFFFFFFFu, s0, 1);
        s0 += __shfl_xor_sync(0xFFFFFFFFu, s0, 2);
        s1 += __shfl_xor_sync(0xFFFFFFFFu, s1, 1);
        s1 += __shfl_xor_sync(0xFFFFFFFFu, s1, 2);
        if (cq == 0) {
            int slot = blockIdx.x * 4 + wn;
            g_normp[(size_t)row0 * 32 + slot] = s0;
            g_normp[(size_t)(row0 + 8) * 32 + slot] = s1;
        }
    }
}

// ---------------- 5) hbar partials: grid (BS, 1, 8), float4 loads ----------------
__global__ __launch_bounds__(256) void hbar_kernel(const float* __restrict__ h) {
    int b = blockIdx.x, s = blockIdx.z;
    int t = threadIdx.x;
    __shared__ float cs[16];
    if (t < 16) cs[t] = g_w[b * PP + s * 16 + t];
    __syncthreads();
    const float4* sp = (const float4*)(h + ((size_t)b * PP + s * 16) * DD) + t;
    float4 acc = {0.f, 0.f, 0.f, 0.f};
#pragma unroll
    for (int p = 0; p < 16; p++) {
        float4 v = sp[(size_t)p * 256];
        float c = cs[p];
        acc.x += c * v.x; acc.y += c * v.y; acc.z += c * v.z; acc.w += c * v.w;
    }
    ((float4*)&g_hbarp[((s * BS + b) << 10)])[t] = acc;
}

// ---------------- 6) eligK partials + inline coefK: grid (BS, 2, 8) ----------------
__global__ __launch_bounds__(256) void eligk_kernel() {
    int b = blockIdx.x, s = blockIdx.z;
    int d2 = blockIdx.y * 256 + threadIdx.x;  // half2 index 0..511
    __shared__ float cs[16];
    if (threadIdx.x < 16) {
        int row = b * PP + s * 16 + threadIdx.x;
        const float* p = &g_normp[row * 32];
        float ss = 0.0f;
#pragma unroll
        for (int i = 0; i < 32; i++) ss += p[i];
        cs[threadIdx.x] = g_w[row] / fmaxf(sqrtf(ss), 1e-8f);
    }
    __syncthreads();
    const __half2* sp = (const __half2*)g_Ch + ((size_t)b * PP + s * 16) * (DD / 2) + d2;
    float2 acc = {0.f, 0.f};
#pragma unroll
    for (int p = 0; p < 16; p++) {
        float2 v = __half22float2(sp[(size_t)p * (DD / 2)]);
        float c = cs[p];
        acc.x += c * v.x;
        acc.y += c * v.y;
    }
    int base = ((s * BS + b) << 10) + d2 * 2;
    g_eligKp[base] = acc.x;
    g_eligKp[base + 1] = acc.y;
}

// ---------------- 7) eligV split-K partials: grid (8 col-chunks, 16 k-chunks) ----------------
__global__ __launch_bounds__(256) void vgemm_kernel(const float* __restrict__ Wv) {
    __shared__ float hs[BS][64];       // 8 KB
    __shared__ float red[BS][128];     // 16 KB
    int ec = blockIdx.x, kc = blockIdx.y;
    int k0 = kc * 64;
    int t = threadIdx.x;
    int col = ec * 128 + (t & 127);
    int half = t >> 7;                 // k-subrange 0/1

    for (int i = t; i < BS * 64; i += 256) {
        int b = i >> 6, k = i & 63;
        float v = 0.0f;
#pragma unroll
        for (int s = 0; s < 8; s++) v += g_hbarp[((s * BS + b) << 10) + k0 + k];
        hs[b][k] = v;
    }
    __syncthreads();

    float acc[BS];
#pragma unroll
    for (int b = 0; b < BS; b++) acc[b] = 0.0f;
#pragma unroll 4
    for (int k = 0; k < 32; k++) {
        int kk = half * 32 + k;
        float wv = Wv[(size_t)(k0 + kk) * DD + col];
#pragma unroll
        for (int b = 0; b < BS; b++) acc[b] += hs[b][kk] * wv;
    }
    if (half == 0) {
#pragma unroll
        for (int b = 0; b < BS; b++) red[b][t] = acc[b];
    }
    __syncthreads();
    if (half == 1) {
        int tc = t & 127;
#pragma unroll
        for (int b = 0; b < BS; b++)
            g_eligVp[((kc * BS + b) << 10) + col] = red[b][tc] + acc[b];
    }
}

// ---------------- 8) expand to [BS,R,D] outputs ----------------
__global__ __launch_bounds__(256) void expand_kernel(const float* __restrict__ eK0,
                                                     const float* __restrict__ eV0,
                                                     const float* __restrict__ bv,
                                                     float* __restrict__ outK,
                                                     float* __restrict__ outV) {
    int idx = blockIdx.x * 256 + threadIdx.x;
    if (idx >= BS * RR * DD) return;
    int b = idx / (RR * DD);
    int d = idx & (DD - 1);
    float A = g_Atot[b];
    float ek = 0.0f;
#pragma unroll
    for (int s = 0; s < 8; s++) ek += g_eligKp[((s * BS + b) << 10) + d];
    float ev = g_wsum[b] * bv[d];
#pragma unroll
    for (int kc = 0; kc < 16; kc++) ev += g_eligVp[((kc * BS + b) << 10) + d];
    outK[idx] = A * eK0[idx] + ek;
    outV[idx] = A * eV0[idx] + ev;
}

// ---------------- launch ----------------
extern "C" void kernel_launch(void* const* d_in, const int* in_sizes, int n_in,
                              void* d_out, int out_size) {
    const float* x = (const float*)d_in[0];
    const float* h = (const float*)d_in[1];
    const float* sur = (const float*)d_in[2];
    const unsigned int* mask = (const unsigned int*)d_in[3];
    const float* pmK = (const float*)d_in[4];
    const float* pmV = (const float*)d_in[5];
    const float* pa = (const float*)d_in[6];
    const float* eK0 = (const float*)d_in[7];
    const float* eV0 = (const float*)d_in[8];
    const float* Wk = (const float*)d_in[9];
    const float* bk = (const float*)d_in[10];
    const float* Wv = (const float*)d_in[11];
    const float* bv = (const float*)d_in[12];

    float* out = (float*)d_out;
    float* y = out;
    float* outK = out + (size_t)BS * PP * DD;
    float* outV = outK + (size_t)BS * RR * DD;

    static const int READOUT_SMEM = RR * DD * 2 * (int)sizeof(float);
    cudaFuncSetAttribute(readout_kernel,
                         cudaFuncAttributeMaxDynamicSharedMemorySize, READOUT_SMEM);
    cudaFuncSetAttribute(mma_gemm_kernel,
                         cudaFuncAttributeMaxDynamicSharedMemorySize, GSMEM);

    coeff_kernel<<<BS, PP>>>(sur, mask);
    convA_kernel<<<MM * DD / 8 / 256, 256>>>(x);
    convB_kernel<<<DD * DD / 8 / 256, 256>>>(Wk);
    readout_kernel<<<dim3(BS, PP / 32), 256, READOUT_SMEM>>>(x, pmK, pmV, pa, y);
    mma_gemm_kernel<<<dim3(DD / 128, MM / 128), 256, GSMEM>>>(bk);
    hbar_kernel<<<dim3(BS, 1, 8), 256>>>(h);
    eligk_kernel<<<dim3(BS, 2, 8), 256>>>();
    vgemm_kernel<<<dim3(8, 16), 256>>>(Wv);
    expand_kernel<<<(BS * RR * DD + 255) / 256, 256>>>(eK0, eV0, bv, outK, outV);
}

// round 14
// speedup vs baseline: 4.7143x; 1.1429x over previous
#include <cuda_runtime.h>
#include <cuda_fp16.h>
#include <cstdint>

#define BS 32
#define PP 128
#define RR 16
#define DD 1024
#define RHO 0.97f
#define MM (BS * PP)   // 4096 rows of the big GEMM

// ---------------- scratch (no allocations allowed) ----------------
__device__ __half g_Ch[(size_t)MM * DD];             // k_cand fp16 (8 MB)
__device__ __half g_Ah[(size_t)MM * DD];             // x fp16 (8 MB)
__device__ __half g_Bh[(size_t)DD * DD];             // Wk fp16 [K][N] (2 MB)
__device__ float g_normp[MM * 32];                   // per-row sumsq partials
__device__ float g_w[MM];
__device__ float g_Atot[BS];
__device__ float g_wsum[BS];
__device__ float g_hbarp[8 * BS * DD];               // p-split partials
__device__ float g_eligKp[8 * BS * DD];              // p-split partials
__device__ float g_eligVp[16 * BS * DD];             // k-split partials

// ---------------- PTX helpers ----------------
__device__ __forceinline__ uint32_t smem_u32(const void* p) {
    return (uint32_t)__cvta_generic_to_shared(p);
}
__device__ __forceinline__ void cp_async16(uint32_t dst, const void* src) {
    asm volatile("cp.async.cg.shared.global [%0], [%1], 16;" :: "r"(dst), "l"(src));
}
#define CP_COMMIT() asm volatile("cp.async.commit_group;" ::: "memory")
#define CP_WAIT2()  asm volatile("cp.async.wait_group 2;" ::: "memory")
#define CP_WAIT0()  asm volatile("cp.async.wait_group 0;" ::: "memory")

__device__ __forceinline__ void ldm_x4(uint32_t* r, uint32_t addr) {
    asm volatile("ldmatrix.sync.aligned.m8n8.x4.shared.b16 {%0,%1,%2,%3}, [%4];"
                 : "=r"(r[0]), "=r"(r[1]), "=r"(r[2]), "=r"(r[3]) : "r"(addr));
}
__device__ __forceinline__ void ldm_x4_t(uint32_t& r0, uint32_t& r1, uint32_t& r2,
                                         uint32_t& r3, uint32_t addr) {
    asm volatile("ldmatrix.sync.aligned.m8n8.x4.trans.shared.b16 {%0,%1,%2,%3}, [%4];"
                 : "=r"(r0), "=r"(r1), "=r"(r2), "=r"(r3) : "r"(addr));
}
__device__ __forceinline__ void mma_f16(float* c, const uint32_t* a, const uint32_t* b) {
    asm volatile("mma.sync.aligned.m16n8k16.row.col.f32.f16.f16.f32 "
                 "{%0,%1,%2,%3}, {%4,%5,%6,%7}, {%8,%9}, {%0,%1,%2,%3};"
                 : "+f"(c[0]), "+f"(c[1]), "+f"(c[2]), "+f"(c[3])
                 : "r"(a[0]), "r"(a[1]), "r"(a[2]), "r"(a[3]), "r"(b[0]), "r"(b[1]));
}

// ---------------- 1) per-batch coefficients ----------------
__global__ void coeff_kernel(const float* __restrict__ surprise,
                             const unsigned int* __restrict__ mask) {
    int b = blockIdx.x, p = threadIdx.x;  // 128 threads
    __shared__ float a_s[PP], c_s[PP], w_s[PP];
    float g = fminf(fmaxf(surprise[b * PP + p] * 0.2f, 0.0f), 1.0f);
    float a = (mask[b * PP + p] != 0u) ? 0.0f : RHO;
    a_s[p] = a;
    __syncthreads();
    if (p == 0) {
        float c = 1.0f;
        for (int q = PP - 1; q >= 0; --q) { c_s[q] = c; c *= a_s[q]; }
        g_Atot[b] = c;
    }
    __syncthreads();
    float w = g * c_s[p];
    w_s[p] = w;
    g_w[b * PP + p] = w;
    __syncthreads();
    if (p == 0) {
        float s = 0.0f;
        for (int q = 0; q < PP; q++) s += w_s[q];
        g_wsum[b] = s;
    }
}

// ---------------- 2) fp32 -> fp16 conversions (8 elems/thread) ----------------
__global__ __launch_bounds__(256) void convA_kernel(const float* __restrict__ x) {
    size_t i8 = (size_t)blockIdx.x * 256 + threadIdx.x;  // over MM*DD/8
    const float4* xf = (const float4*)x;
    float4 a = xf[i8 * 2], b = xf[i8 * 2 + 1];
    __half2 h0 = __floats2half2_rn(a.x, a.y);
    __half2 h1 = __floats2half2_rn(a.z, a.w);
    __half2 h2 = __floats2half2_rn(b.x, b.y);
    __half2 h3 = __floats2half2_rn(b.z, b.w);
    *(uint4*)&g_Ah[i8 * 8] = make_uint4(*(uint32_t*)&h0, *(uint32_t*)&h1,
                                        *(uint32_t*)&h2, *(uint32_t*)&h3);
}
__global__ __launch_bounds__(256) void convB_kernel(const float* __restrict__ Wk) {
    size_t i8 = (size_t)blockIdx.x * 256 + threadIdx.x;  // over DD*DD/8
    const float4* xf = (const float4*)Wk;
    float4 a = xf[i8 * 2], b = xf[i8 * 2 + 1];
    __half2 h0 = __floats2half2_rn(a.x, a.y);
    __half2 h1 = __floats2half2_rn(a.z, a.w);
    __half2 h2 = __floats2half2_rn(b.x, b.y);
    __half2 h3 = __floats2half2_rn(b.z, b.w);
    *(uint4*)&g_Bh[i8 * 8] = make_uint4(*(uint32_t*)&h0, *(uint32_t*)&h1,
                                        *(uint32_t*)&h2, *(uint32_t*)&h3);
}

// ---------------- 3) readout: y_pm (depends only on raw inputs) ----------------
// #pragma unroll 2 on the inner c-loops caps in-flight float4 loads, cutting
// register pressure (R9: regs=255, occ 12%) to allow 2 CTAs/SM.
__global__ __launch_bounds__(256) void readout_kernel(const float* __restrict__ x,
                                                      const float* __restrict__ pmK,
                                                      const float* __restrict__ pmV,
                                                      const float* __restrict__ pa,
                                                      float* __restrict__ y) {
    extern __shared__ float sm[];
    float* Ks = sm;
    float* Vs = sm + RR * DD;
    __shared__ float pas[RR];
    int b = blockIdx.x;
    int tid = threadIdx.x;

    const float4* Kg = (const float4*)(pmK + (size_t)b * RR * DD);
    const float4* Vg = (const float4*)(pmV + (size_t)b * RR * DD);
    float4* K4 = (float4*)Ks;
    float4* V4 = (float4*)Vs;
    for (int i = tid; i < RR * DD / 4; i += 256) {
        K4[i] = Kg[i];
        V4[i] = Vg[i];
    }
    if (tid < RR) pas[tid] = pa[b * RR + tid];
    __syncthreads();

    int warp = tid >> 5, lane = tid & 31;
    for (int t0 = 0; t0 < 32; t0 += 8) {
        int p = blockIdx.y * 32 + t0 + warp;
        const float4* xr = (const float4*)(x + ((size_t)b * PP + p) * DD);
        float nrm = 0.0f;
        float dot[16];
#pragma unroll
        for (int r = 0; r < 16; r++) dot[r] = 0.0f;
#pragma unroll 2
        for (int c = 0; c < 8; c++) {
            float4 v = xr[c * 32 + lane];
            nrm += v.x * v.x + v.y * v.y + v.z * v.z + v.w * v.w;
#pragma unroll
            for (int r = 0; r < 16; r++) {
                float4 kv = ((const float4*)(Ks + r * DD))[c * 32 + lane];
                dot[r] += v.x * kv.x + v.y * kv.y + v.z * kv.z + v.w * kv.w;
            }
        }
#pragma unroll
        for (int off = 16; off; off >>= 1) {
            nrm += __shfl_xor_sync(0xFFFFFFFFu, nrm, off);
#pragma unroll
            for (int r = 0; r < 16; r++)
                dot[r] += __shfl_xor_sync(0xFFFFFFFFu, dot[r], off);
        }
        float inv = 1.0f / fmaxf(sqrtf(nrm), 1e-8f);
        float w[16];
#pragma unroll
        for (int r = 0; r < 16; r++) w[r] = pas[r] * dot[r] * inv;

        float4* yo = (float4*)(y + ((size_t)b * PP + p) * DD);
#pragma unroll 2
        for (int c = 0; c < 8; c++) {
            float4 acc = {0.f, 0.f, 0.f, 0.f};
#pragma unroll
            for (int r = 0; r < 16; r++) {
                float4 vv = ((const float4*)(Vs + r * DD))[c * 32 + lane];
                acc.x += w[r] * vv.x;
                acc.y += w[r] * vv.y;
                acc.z += w[r] * vv.z;
                acc.w += w[r] * vv.w;
            }
            yo[c * 32 + lane] = acc;
        }
    }
}

// ---------------- 4) single-fp16 mma.sync GEMM, 4-stage cp.async ----------------
#define ASTB 80
#define BSTB 272
#define ASTG_A 10240
#define STAGE_B 18944
#define NSTAGE 4
#define GSMEM (NSTAGE * STAGE_B)

__global__ __launch_bounds__(256) void mma_gemm_kernel(const float* __restrict__ bias) {
    extern __shared__ char smem[];
    uint32_t sb = smem_u32(smem);
    int tid = threadIdx.x;
    int lane = tid & 31, warp = tid >> 5;
    int wm = warp >> 2, wn = warp & 3;
    int bm = blockIdx.y * 128, bn = blockIdx.x * 128;

    float acc[4][4][4];
#pragma unroll
    for (int i = 0; i < 4; i++)
#pragma unroll
        for (int j = 0; j < 4; j++)
#pragma unroll
            for (int k = 0; k < 4; k++) acc[i][j][k] = 0.0f;

    int aid0 = tid * 2;
    int arow0 = aid0 >> 2, ach0 = aid0 & 3;
    int arow1 = (aid0 + 1) >> 2, ach1 = (aid0 + 1) & 3;
    int brow0 = aid0 >> 4, bch0 = aid0 & 15;
    int brow1 = (aid0 + 1) >> 4, bch1 = (aid0 + 1) & 15;

    auto issue_stage = [&](int kt, int slot) {
        int ak = kt * 32;
        uint32_t sA = sb + slot * STAGE_B;
        uint32_t sB = sA + ASTG_A;
        cp_async16(sA + arow0 * ASTB + ach0 * 16,
                   &g_Ah[(size_t)(bm + arow0) * 1024 + ak + ach0 * 8]);
        cp_async16(sA + arow1 * ASTB + ach1 * 16,
                   &g_Ah[(size_t)(bm + arow1) * 1024 + ak + ach1 * 8]);
        cp_async16(sB + brow0 * BSTB + bch0 * 16,
                   &g_Bh[(size_t)(ak + brow0) * 1024 + bn + bch0 * 8]);
        cp_async16(sB + brow1 * BSTB + bch1 * 16,
                   &g_Bh[(size_t)(ak + brow1) * 1024 + bn + bch1 * 8]);
    };

    int g8 = lane >> 3;
    int r8 = lane & 7;
    int aRowOff = wm * 64 + r8 + (g8 & 1) * 8;
    int aColB = (g8 >> 1) * 16;
    int bRowOff = r8 + (g8 & 1) * 8;
    int bColB = (wn * 32 + (g8 >> 1) * 8) * 2;

#pragma unroll
    for (int i = 0; i < NSTAGE - 1; i++) {
        issue_stage(i, i);
        CP_COMMIT();
    }

    for (int i = 0; i < 32; i++) {
        CP_WAIT2();
        __syncthreads();
        int slot = i & (NSTAGE - 1);
        uint32_t sA = sb + slot * STAGE_B;
        uint32_t sB = sA + ASTG_A;
#pragma unroll
        for (int ks = 0; ks < 32; ks += 16) {
            uint32_t afr[4][4], bfr[4][2];
#pragma unroll
            for (int tm = 0; tm < 4; tm++)
                ldm_x4(afr[tm], sA + (aRowOff + tm * 16) * ASTB + aColB + ks * 2);
#pragma unroll
            for (int tp = 0; tp < 2; tp++) {
                uint32_t r0, r1, r2, r3;
                ldm_x4_t(r0, r1, r2, r3,
                         sB + (bRowOff + ks) * BSTB + bColB + tp * 32);
                bfr[tp * 2][0] = r0; bfr[tp * 2][1] = r1;
                bfr[tp * 2 + 1][0] = r2; bfr[tp * 2 + 1][1] = r3;
            }
#pragma unroll
            for (int tm = 0; tm < 4; tm++)
#pragma unroll
                for (int tn = 0; tn < 4; tn++)
                    mma_f16(acc[tm][tn], afr[tm], bfr[tn]);
        }
        if (i + NSTAGE - 1 < 32) issue_stage(i + NSTAGE - 1, (i + NSTAGE - 1) & (NSTAGE - 1));
        CP_COMMIT();
    }
    CP_WAIT0();

    int gq = lane >> 2;
    int cq = lane & 3;
#pragma unroll
    for (int tm = 0; tm < 4; tm++) {
        int row0 = bm + wm * 64 + tm * 16 + gq;
        float s0 = 0.0f, s1 = 0.0f;
#pragma unroll
        for (int tn = 0; tn < 4; tn++) {
            int col = bn + wn * 32 + tn * 8 + cq * 2;
            float2 bb = *(const float2*)&bias[col];
            float v0 = acc[tm][tn][0] + bb.x;
            float v1 = acc[tm][tn][1] + bb.y;
            float v2 = acc[tm][tn][2] + bb.x;
            float v3 = acc[tm][tn][3] + bb.y;
            *(__half2*)&g_Ch[(size_t)row0 * DD + col] = __floats2half2_rn(v0, v1);
            *(__half2*)&g_Ch[(size_t)(row0 + 8) * DD + col] = __floats2half2_rn(v2, v3);
            s0 += v0 * v0 + v1 * v1;
            s1 += v2 * v2 + v3 * v3;
        }
        s0 += __shfl_xor_sync(0xFFFFFFFFu, s0, 1);
        s0 += __shfl_xor_sync(0xFFFFFFFFu, s0, 2);
        s1 += __shfl_xor_sync(0xFFFFFFFFu, s1, 1);
        s1 += __shfl_xor_sync(0xFFFFFFFFu, s1, 2);
        if (cq == 0) {
            int slot = blockIdx.x * 4 + wn;
            g_normp[(size_t)row0 * 32 + slot] = s0;
            g_normp[(size_t)(row0 + 8) * 32 + slot] = s1;
        }
    }
}

// ---------------- 5) hbar partials: grid (BS, 1, 8), float4 loads ----------------
__global__ __launch_bounds__(256) void hbar_kernel(const float* __restrict__ h) {
    int b = blockIdx.x, s = blockIdx.z;
    int t = threadIdx.x;
    __shared__ float cs[16];
    if (t < 16) cs[t] = g_w[b * PP + s * 16 + t];
    __syncthreads();
    const float4* sp = (const float4*)(h + ((size_t)b * PP + s * 16) * DD) + t;
    float4 acc = {0.f, 0.f, 0.f, 0.f};
#pragma unroll
    for (int p = 0; p < 16; p++) {
        float4 v = sp[(size_t)p * 256];
        float c = cs[p];
        acc.x += c * v.x; acc.y += c * v.y; acc.z += c * v.z; acc.w += c * v.w;
    }
    ((float4*)&g_hbarp[((s * BS + b) << 10)])[t] = acc;
}

// ---------------- 6) eligK partials + inline coefK: grid (BS, 2, 8) ----------------
__global__ __launch_bounds__(256) void eligk_kernel() {
    int b = blockIdx.x, s = blockIdx.z;
    int d2 = blockIdx.y * 256 + threadIdx.x;  // half2 index 0..511
    __shared__ float cs[16];
    if (threadIdx.x < 16) {
        int row = b * PP + s * 16 + threadIdx.x;
        const float* p = &g_normp[row * 32];
        float ss = 0.0f;
#pragma unroll
        for (int i = 0; i < 32; i++) ss += p[i];
        cs[threadIdx.x] = g_w[row] / fmaxf(sqrtf(ss), 1e-8f);
    }
    __syncthreads();
    const __half2* sp = (const __half2*)g_Ch + ((size_t)b * PP + s * 16) * (DD / 2) + d2;
    float2 acc = {0.f, 0.f};
#pragma unroll
    for (int p = 0; p < 16; p++) {
        float2 v = __half22float2(sp[(size_t)p * (DD / 2)]);
        float c = cs[p];
        acc.x += c * v.x;
        acc.y += c * v.y;
    }
    int base = ((s * BS + b) << 10) + d2 * 2;
    g_eligKp[base] = acc.x;
    g_eligKp[base + 1] = acc.y;
}

// ---------------- 7) eligV split-K partials: grid (8 col-chunks, 16 k-chunks) ----------------
__global__ __launch_bounds__(256) void vgemm_kernel(const float* __restrict__ Wv) {
    __shared__ float hs[BS][64];       // 8 KB
    __shared__ float red[BS][128];     // 16 KB
    int ec = blockIdx.x, kc = blockIdx.y;
    int k0 = kc * 64;
    int t = threadIdx.x;
    int col = ec * 128 + (t & 127);
    int half = t >> 7;                 // k-subrange 0/1

    for (int i = t; i < BS * 64; i += 256) {
        int b = i >> 6, k = i & 63;
        float v = 0.0f;
#pragma unroll
        for (int s = 0; s < 8; s++) v += g_hbarp[((s * BS + b) << 10) + k0 + k];
        hs[b][k] = v;
    }
    __syncthreads();

    float acc[BS];
#pragma unroll
    for (int b = 0; b < BS; b++) acc[b] = 0.0f;
#pragma unroll 4
    for (int k = 0; k < 32; k++) {
        int kk = half * 32 + k;
        float wv = Wv[(size_t)(k0 + kk) * DD + col];
#pragma unroll
        for (int b = 0; b < BS; b++) acc[b] += hs[b][kk] * wv;
    }
    if (half == 0) {
#pragma unroll
        for (int b = 0; b < BS; b++) red[b][t] = acc[b];
    }
    __syncthreads();
    if (half == 1) {
        int tc = t & 127;
#pragma unroll
        for (int b = 0; b < BS; b++)
            g_eligVp[((kc * BS + b) << 10) + col] = red[b][tc] + acc[b];
    }
}

// ---------------- 8) expand to [BS,R,D] outputs ----------------
__global__ __launch_bounds__(256) void expand_kernel(const float* __restrict__ eK0,
                                                     const float* __restrict__ eV0,
                                                     const float* __restrict__ bv,
                                                     float* __restrict__ outK,
                                                     float* __restrict__ outV) {
    int idx = blockIdx.x * 256 + threadIdx.x;
    if (idx >= BS * RR * DD) return;
    int b = idx / (RR * DD);
    int d = idx & (DD - 1);
    float A = g_Atot[b];
    float ek = 0.0f;
#pragma unroll
    for (int s = 0; s < 8; s++) ek += g_eligKp[((s * BS + b) << 10) + d];
    float ev = g_wsum[b] * bv[d];
#pragma unroll
    for (int kc = 0; kc < 16; kc++) ev += g_eligVp[((kc * BS + b) << 10) + d];
    outK[idx] = A * eK0[idx] + ek;
    outV[idx] = A * eV0[idx] + ev;
}

// ---------------- launch ----------------
extern "C" void kernel_launch(void* const* d_in, const int* in_sizes, int n_in,
                              void* d_out, int out_size) {
    const float* x = (const float*)d_in[0];
    const float* h = (const float*)d_in[1];
    const float* sur = (const float*)d_in[2];
    const unsigned int* mask = (const unsigned int*)d_in[3];
    const float* pmK = (const float*)d_in[4];
    const float* pmV = (const float*)d_in[5];
    const float* pa = (const float*)d_in[6];
    const float* eK0 = (const float*)d_in[7];
    const float* eV0 = (const float*)d_in[8];
    const float* Wk = (const float*)d_in[9];
    const float* bk = (const float*)d_in[10];
    const float* Wv = (const float*)d_in[11];
    const float* bv = (const float*)d_in[12];

    float* out = (float*)d_out;
    float* y = out;
    float* outK = out + (size_t)BS * PP * DD;
    float* outV = outK + (size_t)BS * RR * DD;

    static const int READOUT_SMEM = RR * DD * 2 * (int)sizeof(float);
    cudaFuncSetAttribute(readout_kernel,
                         cudaFuncAttributeMaxDynamicSharedMemorySize, READOUT_SMEM);
    cudaFuncSetAttribute(mma_gemm_kernel,
                         cudaFuncAttributeMaxDynamicSharedMemorySize, GSMEM);

    coeff_kernel<<<BS, PP>>>(sur, mask);
    convA_kernel<<<MM * DD / 8 / 256, 256>>>(x);
    convB_kernel<<<DD * DD / 8 / 256, 256>>>(Wk);
    readout_kernel<<<dim3(BS, PP / 32), 256, READOUT_SMEM>>>(x, pmK, pmV, pa, y);
    mma_gemm_kernel<<<dim3(DD / 128, MM / 128), 256, GSMEM>>>(bk);
    hbar_kernel<<<dim3(BS, 1, 8), 256>>>(h);
    eligk_kernel<<<dim3(BS, 2, 8), 256>>>();
    vgemm_kernel<<<dim3(8, 16), 256>>>(Wv);
    expand_kernel<<<(BS * RR * DD + 255) / 256, 256>>>(eK0, eV0, bv, outK, outV);
}